// round 1
// baseline (speedup 1.0000x reference)
#include <cuda_runtime.h>
#include <math.h>
#include <stdint.h>

#define NN   50000
#define EE   800000
#define ETOT (NN + EE)     // 850000 edges incl self loops
#define IND  256
#define HIDD 72

// ------------------------- scratch (device globals, no allocs) -------------
__device__ int   g_rowptr[NN + 1];     // degree -> exclusive scan (in place)
__device__ int   g_cursor[NN];
__device__ int   g_csr[ETOT];          // src node per CSR slot (sorted by dst)
__device__ float g_x0[NN * HIDD];
__device__ float g_h1[NN * 288];
__device__ float g_o1[NN * 288];
__device__ float g_h2[NN * HIDD];
__device__ float g_o2[NN * HIDD];
__device__ float g_h3[NN * HIDD];
__device__ float g_o3[NN * HIDD];
__device__ float g_ls1[NN * 4];
__device__ float g_ld1[NN * 4];
__device__ float g_ls2[NN];
__device__ float g_ld2[NN];
__device__ float g_ls3[NN];
__device__ float g_ld3[NN];
__device__ float g_p[(size_t)ETOT * 4];  // per-edge exp() scratch

// ------------------------------ CSR build ----------------------------------
__global__ void k_init_deg() {
    int i = blockIdx.x * blockDim.x + threadIdx.x;
    if (i < NN) g_rowptr[i] = 1;   // self loop counted up front
}

__global__ void k_count_deg(const int* __restrict__ ei) {
    int e = blockIdx.x * blockDim.x + threadIdx.x;
    if (e < EE) atomicAdd(&g_rowptr[ei[EE + e]], 1);
}

// single-block exclusive scan of g_rowptr[0..NN) in place; g_rowptr[NN]=total
__global__ void k_scan() {
    __shared__ int wsum[32];
    __shared__ int carry;
    int tid = threadIdx.x, lane = tid & 31, wid = tid >> 5;
    if (tid == 0) carry = 0;
    __syncthreads();
    for (int base = 0; base < NN; base += 1024) {
        int idx = base + tid;
        int v = (idx < NN) ? g_rowptr[idx] : 0;
        int x = v;
        #pragma unroll
        for (int o = 1; o < 32; o <<= 1) {
            int y = __shfl_up_sync(0xffffffffu, x, o);
            if (lane >= o) x += y;
        }
        if (lane == 31) wsum[wid] = x;
        __syncthreads();
        if (wid == 0) {
            int s = wsum[lane];
            #pragma unroll
            for (int o = 1; o < 32; o <<= 1) {
                int y = __shfl_up_sync(0xffffffffu, s, o);
                if (lane >= o) s += y;
            }
            wsum[lane] = s;
        }
        __syncthreads();
        int pre  = (wid > 0) ? wsum[wid - 1] : 0;
        int excl = carry + pre + x - v;
        if (idx < NN) g_rowptr[idx] = excl;
        int total = wsum[31];
        __syncthreads();
        if (tid == 0) carry += total;
        __syncthreads();
    }
    if (threadIdx.x == 0) g_rowptr[NN] = carry;
}

__global__ void k_selfloop() {
    int i = blockIdx.x * blockDim.x + threadIdx.x;
    if (i < NN) {
        int r = g_rowptr[i];
        g_csr[r] = i;             // self loop first in each segment
        g_cursor[i] = r + 1;
    }
}

__global__ void k_scatter(const int* __restrict__ ei) {
    int e = blockIdx.x * blockDim.x + threadIdx.x;
    if (e < EE) {
        int s = ei[e];
        int d = ei[EE + e];
        int pos = atomicAdd(&g_cursor[d], 1);
        g_csr[pos] = s;
    }
}

// ------------------------------- GEMM ---------------------------------------
// C[M, KoutTotal] (col tile of 72 per blockIdx.y) = A[M,Kin] @ W[Kin,KoutTotal]
// BM=128, BN=72, BK=8; 256 threads; warp w -> cols [9w,9w+9), lane -> rows lane*4+i
__global__ void __launch_bounds__(256) k_gemm(
    const float* __restrict__ A, const float* __restrict__ W,
    const float* __restrict__ bias, float* __restrict__ C,
    int M, int Kin, int KoutTotal, int useBias)
{
    __shared__ float As[8][128];
    __shared__ float Bs[8][72];
    __shared__ float Cs[32][73];

    int tid = threadIdx.x;
    int w = tid >> 5, lane = tid & 31;
    int r0 = blockIdx.x * 128;
    int c0 = blockIdx.y * 72;

    float acc[4][9];
    #pragma unroll
    for (int i = 0; i < 4; i++)
        #pragma unroll
        for (int j = 0; j < 9; j++) acc[i][j] = 0.f;

    int lrow = tid >> 1;          // 0..127
    int lkk  = (tid & 1) * 4;     // 0 or 4

    for (int k0 = 0; k0 < Kin; k0 += 8) {
        float4 av;
        int gr = r0 + lrow;
        if (gr < M) av = *(const float4*)(A + (size_t)gr * Kin + k0 + lkk);
        else        av = make_float4(0.f, 0.f, 0.f, 0.f);
        As[lkk + 0][lrow] = av.x;
        As[lkk + 1][lrow] = av.y;
        As[lkk + 2][lrow] = av.z;
        As[lkk + 3][lrow] = av.w;
        for (int idx = tid; idx < 8 * 72; idx += 256) {
            int kk = idx / 72, c = idx % 72;
            Bs[kk][c] = W[(size_t)(k0 + kk) * KoutTotal + c0 + c];
        }
        __syncthreads();
        #pragma unroll
        for (int kk = 0; kk < 8; kk++) {
            float4 a = *(const float4*)&As[kk][lane * 4];
            float b[9];
            #pragma unroll
            for (int j = 0; j < 9; j++) b[j] = Bs[kk][w * 9 + j];
            #pragma unroll
            for (int j = 0; j < 9; j++) {
                acc[0][j] += a.x * b[j];
                acc[1][j] += a.y * b[j];
                acc[2][j] += a.z * b[j];
                acc[3][j] += a.w * b[j];
            }
        }
        __syncthreads();
    }

    // staged epilogue: 4 groups of 32 rows, coalesced stores
    for (int g = 0; g < 4; g++) {
        if ((lane >> 3) == g) {
            #pragma unroll
            for (int i = 0; i < 4; i++) {
                int rloc = (lane & 7) * 4 + i;
                #pragma unroll
                for (int j = 0; j < 9; j++) Cs[rloc][w * 9 + j] = acc[i][j];
            }
        }
        __syncthreads();
        for (int idx = tid; idx < 32 * 72; idx += 256) {
            int rr = idx / 72, c = idx % 72;
            int gr2 = r0 + g * 32 + rr;
            if (gr2 < M) {
                float v = Cs[rr][c];
                if (useBias) v += __ldg(bias + c0 + c);
                C[(size_t)gr2 * KoutTotal + c0 + c] = v;
            }
        }
        __syncthreads();
    }
}

// ------------------------------ logits --------------------------------------
__global__ void k_logits4(const float* __restrict__ h,
                          const float* __restrict__ asrc, const float* __restrict__ adst,
                          float* __restrict__ ls, float* __restrict__ ld)
{
    int t = blockIdx.x * blockDim.x + threadIdx.x;
    if (t >= NN * 4) return;
    int n = t >> 2, hh = t & 3;
    const float* row = h + (size_t)n * 288 + hh * 72;
    const float* av = asrc + hh * 72;
    const float* dv = adst + hh * 72;
    float s = 0.f, d = 0.f;
    #pragma unroll
    for (int c = 0; c < 72; c += 4) {
        float4 r = *(const float4*)(row + c);
        float4 a = __ldg((const float4*)(av + c));
        float4 b = __ldg((const float4*)(dv + c));
        s += r.x * a.x + r.y * a.y + r.z * a.z + r.w * a.w;
        d += r.x * b.x + r.y * b.y + r.z * b.z + r.w * b.w;
    }
    ls[t] = s;
    ld[t] = d;
}

__global__ void k_logits1(const float* __restrict__ h,
                          const float* __restrict__ asrc, const float* __restrict__ adst,
                          float* __restrict__ ls, float* __restrict__ ld)
{
    int n = blockIdx.x * blockDim.x + threadIdx.x;
    if (n >= NN) return;
    const float* row = h + (size_t)n * 72;
    float s = 0.f, d = 0.f;
    #pragma unroll
    for (int c = 0; c < 72; c += 4) {
        float4 r = *(const float4*)(row + c);
        float4 a = __ldg((const float4*)(asrc + c));
        float4 b = __ldg((const float4*)(adst + c));
        s += r.x * a.x + r.y * a.y + r.z * a.z + r.w * a.w;
        d += r.x * b.x + r.y * b.y + r.z * b.z + r.w * b.w;
    }
    ls[n] = s;
    ld[n] = d;
}

// --------------------------- GAT edge pass -----------------------------------
// warp per dst node; CSR segments; 3 sub-passes: max, exp-sum (store p), aggregate.
template <int H>
__global__ void __launch_bounds__(256) k_edge(
    const float* __restrict__ hfeat, const float* __restrict__ ls,
    const float* __restrict__ ld, const float* __restrict__ bias,
    float* __restrict__ outp, float* __restrict__ pbuf)
{
    int warp = (blockIdx.x * blockDim.x + threadIdx.x) >> 5;
    if (warp >= NN) return;
    int lane = threadIdx.x & 31;
    int s0 = g_rowptr[warp], s1 = g_rowptr[warp + 1];

    float ldv[H];
    #pragma unroll
    for (int h = 0; h < H; h++) ldv[h] = __ldg(ld + (size_t)warp * H + h);

    // pass 1: segment max of leaky-relu logits
    float m[H];
    #pragma unroll
    for (int h = 0; h < H; h++) m[h] = -1e30f;
    for (int i = s0 + lane; i < s1; i += 32) {
        int s = g_csr[i];
        if (H == 4) {
            float4 lv = __ldg((const float4*)ls + s);
            float v0 = lv.x + ldv[0]; v0 = fmaxf(v0, 0.2f * v0); m[0] = fmaxf(m[0], v0);
            float v1 = lv.y + ldv[1]; v1 = fmaxf(v1, 0.2f * v1); m[1] = fmaxf(m[1], v1);
            float v2 = lv.z + ldv[2]; v2 = fmaxf(v2, 0.2f * v2); m[2] = fmaxf(m[2], v2);
            float v3 = lv.w + ldv[3]; v3 = fmaxf(v3, 0.2f * v3); m[3] = fmaxf(m[3], v3);
        } else {
            float v = __ldg(ls + s) + ldv[0];
            v = fmaxf(v, 0.2f * v);
            m[0] = fmaxf(m[0], v);
        }
    }
    #pragma unroll
    for (int h = 0; h < H; h++)
        #pragma unroll
        for (int o = 16; o > 0; o >>= 1)
            m[h] = fmaxf(m[h], __shfl_xor_sync(0xffffffffu, m[h], o));

    // pass 2: exp & segment sum, stash p per edge
    float sum[H];
    #pragma unroll
    for (int h = 0; h < H; h++) sum[h] = 0.f;
    for (int i = s0 + lane; i < s1; i += 32) {
        int s = g_csr[i];
        if (H == 4) {
            float4 lv = __ldg((const float4*)ls + s);
            float v0 = lv.x + ldv[0]; v0 = fmaxf(v0, 0.2f * v0);
            float v1 = lv.y + ldv[1]; v1 = fmaxf(v1, 0.2f * v1);
            float v2 = lv.z + ldv[2]; v2 = fmaxf(v2, 0.2f * v2);
            float v3 = lv.w + ldv[3]; v3 = fmaxf(v3, 0.2f * v3);
            float4 pv;
            pv.x = __expf(v0 - m[0]); pv.y = __expf(v1 - m[1]);
            pv.z = __expf(v2 - m[2]); pv.w = __expf(v3 - m[3]);
            ((float4*)pbuf)[i] = pv;
            sum[0] += pv.x; sum[1] += pv.y; sum[2] += pv.z; sum[3] += pv.w;
        } else {
            float v = __ldg(ls + s) + ldv[0];
            v = fmaxf(v, 0.2f * v);
            float p = __expf(v - m[0]);
            pbuf[i] = p;
            sum[0] += p;
        }
    }
    #pragma unroll
    for (int h = 0; h < H; h++)
        #pragma unroll
        for (int o = 16; o > 0; o >>= 1)
            sum[h] += __shfl_xor_sync(0xffffffffu, sum[h], o);
    float inv[H];
    #pragma unroll
    for (int h = 0; h < H; h++) inv[h] = 1.f / fmaxf(sum[h], 1e-16f);

    // pass 3: weighted feature aggregation (lanes over channels, warp walks edges)
    const int CH  = H * 72;
    const int NCH = (CH + 31) / 32;
    float acc[NCH];
    #pragma unroll
    for (int k = 0; k < NCH; k++) acc[k] = 0.f;

    for (int i = s0; i < s1; i++) {
        int s = g_csr[i];
        const float* hr = hfeat + (size_t)s * CH;
        if (H == 4) {
            float4 pv = __ldg((const float4*)pbuf + i);
            float a0 = pv.x * inv[0], a1 = pv.y * inv[1];
            float a2 = pv.z * inv[2], a3 = pv.w * inv[3];
            #pragma unroll
            for (int k = 0; k < 9; k++) {
                int c = k * 32 + lane;
                float a = (c < 72) ? a0 : (c < 144) ? a1 : (c < 216) ? a2 : a3;
                acc[k] += a * __ldg(hr + c);
            }
        } else {
            float a = __ldg(pbuf + i) * inv[0];
            acc[0] += a * __ldg(hr + lane);
            acc[1] += a * __ldg(hr + 32 + lane);
            if (lane < 8) acc[2] += a * __ldg(hr + 64 + lane);
        }
    }

    // epilogue: +bias, ELU, store
    #pragma unroll
    for (int k = 0; k < NCH; k++) {
        int c = k * 32 + lane;
        if (c < CH) {
            float v = acc[k] + __ldg(bias + c);
            outp[(size_t)warp * CH + c] = (v > 0.f) ? v : expm1f(v);
        }
    }
}

// ----------------------- final residual + score MLP -------------------------
__global__ void __launch_bounds__(256) k_final(
    const float* __restrict__ h3, const float* __restrict__ x0,
    const float* __restrict__ Ws1, const float* __restrict__ bs1,
    const float* __restrict__ Ws2, const float* __restrict__ bs2,
    float* __restrict__ out)
{
    __shared__ float w1s[72 * 32];
    __shared__ float w2s[32];
    __shared__ float b1s[32];
    __shared__ float b2s;
    for (int i = threadIdx.x; i < 72 * 32; i += blockDim.x) w1s[i] = Ws1[i];
    if (threadIdx.x < 32) {
        w2s[threadIdx.x] = Ws2[threadIdx.x];
        b1s[threadIdx.x] = bs1[threadIdx.x];
    }
    if (threadIdx.x == 0) b2s = bs2[0];
    __syncthreads();

    int n = blockIdx.x * blockDim.x + threadIdx.x;
    if (n >= NN) return;
    float t[32];
    #pragma unroll
    for (int j = 0; j < 32; j++) t[j] = b1s[j];
    const float* hr = h3 + (size_t)n * 72;
    const float* xr = x0 + (size_t)n * 72;
    for (int k = 0; k < 72; k++) {
        float v = __ldg(hr + k) + __ldg(xr + k);
        #pragma unroll
        for (int j = 0; j < 32; j += 4) {
            float4 w = *(const float4*)&w1s[k * 32 + j];
            t[j + 0] += v * w.x;
            t[j + 1] += v * w.y;
            t[j + 2] += v * w.z;
            t[j + 3] += v * w.w;
        }
    }
    float s = b2s;
    #pragma unroll
    for (int j = 0; j < 32; j++) s += fmaxf(t[j], 0.f) * w2s[j];
    out[n] = s;
}

// ------------------------------ launch ---------------------------------------
extern "C" void kernel_launch(void* const* d_in, const int* in_sizes, int n_in,
                              void* d_out, int out_size)
{
    const float* x    = (const float*)d_in[0];
    const int*   ei   = (const int*)d_in[1];
    const float* W_in = (const float*)d_in[2];
    const float* b_in = (const float*)d_in[3];
    const float* W1   = (const float*)d_in[4];
    const float* as1  = (const float*)d_in[5];
    const float* ad1  = (const float*)d_in[6];
    const float* b1   = (const float*)d_in[7];
    const float* W2   = (const float*)d_in[8];
    const float* as2  = (const float*)d_in[9];
    const float* ad2  = (const float*)d_in[10];
    const float* b2   = (const float*)d_in[11];
    const float* W3   = (const float*)d_in[12];
    const float* as3  = (const float*)d_in[13];
    const float* ad3  = (const float*)d_in[14];
    const float* b3   = (const float*)d_in[15];
    const float* Ws1  = (const float*)d_in[16];
    const float* bs1  = (const float*)d_in[17];
    const float* Ws2  = (const float*)d_in[18];
    const float* bs2  = (const float*)d_in[19];
    float* out = (float*)d_out;

    float *px0, *ph1, *po1, *ph2, *po2, *ph3, *po3;
    float *pls1, *pld1, *pls2, *pld2, *pls3, *pld3, *pp;
    cudaGetSymbolAddress((void**)&px0,  g_x0);
    cudaGetSymbolAddress((void**)&ph1,  g_h1);
    cudaGetSymbolAddress((void**)&po1,  g_o1);
    cudaGetSymbolAddress((void**)&ph2,  g_h2);
    cudaGetSymbolAddress((void**)&po2,  g_o2);
    cudaGetSymbolAddress((void**)&ph3,  g_h3);
    cudaGetSymbolAddress((void**)&po3,  g_o3);
    cudaGetSymbolAddress((void**)&pls1, g_ls1);
    cudaGetSymbolAddress((void**)&pld1, g_ld1);
    cudaGetSymbolAddress((void**)&pls2, g_ls2);
    cudaGetSymbolAddress((void**)&pld2, g_ld2);
    cudaGetSymbolAddress((void**)&pls3, g_ls3);
    cudaGetSymbolAddress((void**)&pld3, g_ld3);
    cudaGetSymbolAddress((void**)&pp,   g_p);

    // CSR build (reused by all three GAT layers)
    k_init_deg<<<(NN + 255) / 256, 256>>>();
    k_count_deg<<<(EE + 255) / 256, 256>>>(ei);
    k_scan<<<1, 1024>>>();
    k_selfloop<<<(NN + 255) / 256, 256>>>();
    k_scatter<<<(EE + 255) / 256, 256>>>(ei);

    dim3 g1((NN + 127) / 128, 1);
    dim3 g4((NN + 127) / 128, 4);

    // x0 = x @ W_in + b_in
    k_gemm<<<g1, 256>>>(x, W_in, b_in, px0, NN, IND, 72, 1);

    // layer 1 (4 heads, concat)
    k_gemm<<<g4, 256>>>(px0, W1, nullptr, ph1, NN, 72, 288, 0);
    k_logits4<<<(NN * 4 + 255) / 256, 256>>>(ph1, as1, ad1, pls1, pld1);
    k_edge<4><<<(NN * 32) / 256, 256>>>(ph1, pls1, pld1, b1, po1, pp);

    // layer 2 (1 head)
    k_gemm<<<g1, 256>>>(po1, W2, nullptr, ph2, NN, 288, 72, 0);
    k_logits1<<<(NN + 255) / 256, 256>>>(ph2, as2, ad2, pls2, pld2);
    k_edge<1><<<(NN * 32) / 256, 256>>>(ph2, pls2, pld2, b2, po2, pp);

    // layer 3 (1 head)
    k_gemm<<<g1, 256>>>(po2, W3, nullptr, ph3, NN, 72, 72, 0);
    k_logits1<<<(NN + 255) / 256, 256>>>(ph3, as3, ad3, pls3, pld3);
    k_edge<1><<<(NN * 32) / 256, 256>>>(ph3, pls3, pld3, b3, po3, pp);

    // residual + score MLP
    k_final<<<(NN + 255) / 256, 256>>>(po3, px0, Ws1, bs1, Ws2, bs2, out);
}

// round 2
// speedup vs baseline: 1.0078x; 1.0078x over previous
#include <cuda_runtime.h>
#include <math.h>
#include <stdint.h>

#define NN   50000
#define EE   800000
#define ETOT (NN + EE)     // 850000 edges incl self loops
#define IND  256
#define HIDD 72
#define NBLK ((NN + 255) / 256)   // 196

// ------------------------- scratch (device globals, no allocs) -------------
__device__ __align__(16) int   g_rowptr[NN + 1];
__device__ __align__(16) int   g_blksum[NBLK];
__device__ __align__(16) int   g_cursor[NN];
__device__ __align__(16) int   g_csr[ETOT];          // src per CSR slot (grouped by dst)
__device__ __align__(16) float g_x0[NN * HIDD];
__device__ __align__(16) float g_h1[NN * 288];
__device__ __align__(16) float g_o1[NN * 288];
__device__ __align__(16) float g_h2[NN * HIDD];
__device__ __align__(16) float g_o2[NN * HIDD];
__device__ __align__(16) float g_h3[NN * HIDD];
__device__ __align__(16) float g_o3[NN * HIDD];
__device__ __align__(16) float g_ls1[NN * 4];
__device__ __align__(16) float g_ld1[NN * 4];
__device__ __align__(16) float g_ls2[NN];
__device__ __align__(16) float g_ld2[NN];
__device__ __align__(16) float g_ls3[NN];
__device__ __align__(16) float g_ld3[NN];

// ------------------------------ CSR build ----------------------------------
__global__ void k_init_deg() {
    int i = blockIdx.x * blockDim.x + threadIdx.x;
    if (i < NN) g_rowptr[i] = 1;   // self loop counted up front
}

__global__ void k_count_deg(const int* __restrict__ ei) {
    int e = blockIdx.x * blockDim.x + threadIdx.x;
    if (e < EE) atomicAdd(&g_rowptr[ei[EE + e]], 1);
}

// per-block exclusive scan of 256 elems; block total -> g_blksum
__global__ void __launch_bounds__(256) k_scan_blk() {
    __shared__ int wsum[8];
    int tid = threadIdx.x, lane = tid & 31, wid = tid >> 5;
    int idx = blockIdx.x * 256 + tid;
    int v = (idx < NN) ? g_rowptr[idx] : 0;
    int x = v;
    #pragma unroll
    for (int o = 1; o < 32; o <<= 1) {
        int y = __shfl_up_sync(0xffffffffu, x, o);
        if (lane >= o) x += y;
    }
    if (lane == 31) wsum[wid] = x;
    __syncthreads();
    if (wid == 0 && lane < 8) {
        int s = wsum[lane];
        #pragma unroll
        for (int o = 1; o < 8; o <<= 1) {
            int y = __shfl_up_sync(0x000000ffu, s, o);
            if (lane >= o) s += y;
        }
        wsum[lane] = s;
    }
    __syncthreads();
    int excl = (wid ? wsum[wid - 1] : 0) + x - v;
    if (idx < NN) g_rowptr[idx] = excl;
    if (tid == 0) g_blksum[blockIdx.x] = wsum[7];
}

// exclusive scan of the 196 block totals (single block of 256)
__global__ void __launch_bounds__(256) k_scan_top() {
    __shared__ int wsum[8];
    int tid = threadIdx.x, lane = tid & 31, wid = tid >> 5;
    int v = (tid < NBLK) ? g_blksum[tid] : 0;
    int x = v;
    #pragma unroll
    for (int o = 1; o < 32; o <<= 1) {
        int y = __shfl_up_sync(0xffffffffu, x, o);
        if (lane >= o) x += y;
    }
    if (lane == 31) wsum[wid] = x;
    __syncthreads();
    if (wid == 0 && lane < 8) {
        int s = wsum[lane];
        #pragma unroll
        for (int o = 1; o < 8; o <<= 1) {
            int y = __shfl_up_sync(0x000000ffu, s, o);
            if (lane >= o) s += y;
        }
        wsum[lane] = s;
    }
    __syncthreads();
    int excl = (wid ? wsum[wid - 1] : 0) + x - v;
    if (tid < NBLK) g_blksum[tid] = excl;
}

// add block offsets, place self loop first in each segment, init cursor
__global__ void k_add_self() {
    int i = blockIdx.x * blockDim.x + threadIdx.x;
    if (i < NN) {
        int r = g_rowptr[i] + g_blksum[i >> 8];
        g_rowptr[i] = r;
        g_csr[r] = i;
        g_cursor[i] = r + 1;
    }
    if (i == 0) g_rowptr[NN] = ETOT;
}

__global__ void k_scatter(const int* __restrict__ ei) {
    int e = blockIdx.x * blockDim.x + threadIdx.x;
    if (e < EE) {
        int s = ei[e];
        int d = ei[EE + e];
        int pos = atomicAdd(&g_cursor[d], 1);
        g_csr[pos] = s;
    }
}

// ------------------------------- GEMM ---------------------------------------
// C[M, KoutTotal] (col tile of 72 per blockIdx.y) = A[M,Kin] @ W[Kin,KoutTotal]
__global__ void __launch_bounds__(256) k_gemm(
    const float* __restrict__ A, const float* __restrict__ W,
    const float* __restrict__ bias, float* __restrict__ C,
    int M, int Kin, int KoutTotal, int useBias)
{
    __shared__ float As[8][128];
    __shared__ float Bs[8][72];
    __shared__ float Cs[32][73];

    int tid = threadIdx.x;
    int w = tid >> 5, lane = tid & 31;
    int r0 = blockIdx.x * 128;
    int c0 = blockIdx.y * 72;

    float acc[4][9];
    #pragma unroll
    for (int i = 0; i < 4; i++)
        #pragma unroll
        for (int j = 0; j < 9; j++) acc[i][j] = 0.f;

    int lrow = tid >> 1;
    int lkk  = (tid & 1) * 4;

    for (int k0 = 0; k0 < Kin; k0 += 8) {
        float4 av;
        int gr = r0 + lrow;
        if (gr < M) av = *(const float4*)(A + (size_t)gr * Kin + k0 + lkk);
        else        av = make_float4(0.f, 0.f, 0.f, 0.f);
        As[lkk + 0][lrow] = av.x;
        As[lkk + 1][lrow] = av.y;
        As[lkk + 2][lrow] = av.z;
        As[lkk + 3][lrow] = av.w;
        for (int idx = tid; idx < 8 * 72; idx += 256) {
            int kk = idx / 72, c = idx % 72;
            Bs[kk][c] = W[(size_t)(k0 + kk) * KoutTotal + c0 + c];
        }
        __syncthreads();
        #pragma unroll
        for (int kk = 0; kk < 8; kk++) {
            float4 a = *(const float4*)&As[kk][lane * 4];
            float b[9];
            #pragma unroll
            for (int j = 0; j < 9; j++) b[j] = Bs[kk][w * 9 + j];
            #pragma unroll
            for (int j = 0; j < 9; j++) {
                acc[0][j] += a.x * b[j];
                acc[1][j] += a.y * b[j];
                acc[2][j] += a.z * b[j];
                acc[3][j] += a.w * b[j];
            }
        }
        __syncthreads();
    }

    for (int g = 0; g < 4; g++) {
        if ((lane >> 3) == g) {
            #pragma unroll
            for (int i = 0; i < 4; i++) {
                int rloc = (lane & 7) * 4 + i;
                #pragma unroll
                for (int j = 0; j < 9; j++) Cs[rloc][w * 9 + j] = acc[i][j];
            }
        }
        __syncthreads();
        for (int idx = tid; idx < 32 * 72; idx += 256) {
            int rr = idx / 72, c = idx % 72;
            int gr2 = r0 + g * 32 + rr;
            if (gr2 < M) {
                float v = Cs[rr][c];
                if (useBias) v += __ldg(bias + c0 + c);
                C[(size_t)gr2 * KoutTotal + c0 + c] = v;
            }
        }
        __syncthreads();
    }
}

// ------------------------------ logits --------------------------------------
__global__ void k_logits4(const float* __restrict__ h,
                          const float* __restrict__ asrc, const float* __restrict__ adst,
                          float* __restrict__ ls, float* __restrict__ ld)
{
    int t = blockIdx.x * blockDim.x + threadIdx.x;
    if (t >= NN * 4) return;
    int n = t >> 2, hh = t & 3;
    const float* row = h + (size_t)n * 288 + hh * 72;
    const float* av = asrc + hh * 72;
    const float* dv = adst + hh * 72;
    float s = 0.f, d = 0.f;
    #pragma unroll
    for (int c = 0; c < 72; c += 4) {
        float4 r = *(const float4*)(row + c);
        float4 a = __ldg((const float4*)(av + c));
        float4 b = __ldg((const float4*)(dv + c));
        s += r.x * a.x + r.y * a.y + r.z * a.z + r.w * a.w;
        d += r.x * b.x + r.y * b.y + r.z * b.z + r.w * b.w;
    }
    ls[t] = s;
    ld[t] = d;
}

__global__ void k_logits1(const float* __restrict__ h,
                          const float* __restrict__ asrc, const float* __restrict__ adst,
                          float* __restrict__ ls, float* __restrict__ ld)
{
    int n = blockIdx.x * blockDim.x + threadIdx.x;
    if (n >= NN) return;
    const float* row = h + (size_t)n * 72;
    float s = 0.f, d = 0.f;
    #pragma unroll
    for (int c = 0; c < 72; c += 4) {
        float4 r = *(const float4*)(row + c);
        float4 a = __ldg((const float4*)(asrc + c));
        float4 b = __ldg((const float4*)(adst + c));
        s += r.x * a.x + r.y * a.y + r.z * a.z + r.w * a.w;
        d += r.x * b.x + r.y * b.y + r.z * b.z + r.w * b.w;
    }
    ls[n] = s;
    ld[n] = d;
}

// ---------------------- fused GAT edge pass (single sweep) -------------------
// warp per dst node. Softmax is shift-invariant -> skip segment max.
// Aggregate unnormalized (acc += p*h), divide by sum(p) at the end.
// All lanes walk edges together: ls / csr loads are warp-uniform (broadcast).
__global__ void __launch_bounds__(256) k_edge4(
    const float* __restrict__ hfeat, const float* __restrict__ ls,
    const float* __restrict__ ld, const float* __restrict__ bias,
    float* __restrict__ outp)
{
    int node = (blockIdx.x * blockDim.x + threadIdx.x) >> 5;
    if (node >= NN) return;
    int lane = threadIdx.x & 31;
    int s0 = g_rowptr[node], s1 = g_rowptr[node + 1];

    float4 ldv = __ldg((const float4*)ld + node);

    float4 acc0 = make_float4(0.f, 0.f, 0.f, 0.f);
    float4 acc1 = make_float4(0.f, 0.f, 0.f, 0.f);
    float  acc2 = 0.f;
    float  sum0 = 0.f, sum1 = 0.f, sum2 = 0.f, sum3 = 0.f;

    bool h0_is0 = (lane < 18);               // block0: c = 4*lane     (head0 | head1)
    bool h1_is1 = (lane < 4);                // block1: c = 128+4*lane (head1|head2|head3)
    bool h1_is2 = (lane < 22);

    #pragma unroll 4
    for (int i = s0; i < s1; i++) {
        int s = g_csr[i];                     // warp-uniform
        float4 lv = __ldg((const float4*)ls + s);
        float v0 = lv.x + ldv.x; v0 = fmaxf(v0, 0.2f * v0);
        float v1 = lv.y + ldv.y; v1 = fmaxf(v1, 0.2f * v1);
        float v2 = lv.z + ldv.z; v2 = fmaxf(v2, 0.2f * v2);
        float v3 = lv.w + ldv.w; v3 = fmaxf(v3, 0.2f * v3);
        float p0 = __expf(v0), p1 = __expf(v1);
        float p2 = __expf(v2), p3 = __expf(v3);
        sum0 += p0; sum1 += p1; sum2 += p2; sum3 += p3;

        const float* hr = hfeat + (size_t)s * 288;
        float4 hA = __ldg((const float4*)(hr + lane * 4));
        float4 hB = __ldg((const float4*)(hr + 128 + lane * 4));
        float  hC = __ldg(hr + 256 + lane);

        float a0 = h0_is0 ? p0 : p1;
        float a1 = h1_is1 ? p1 : (h1_is2 ? p2 : p3);
        acc0.x += a0 * hA.x; acc0.y += a0 * hA.y;
        acc0.z += a0 * hA.z; acc0.w += a0 * hA.w;
        acc1.x += a1 * hB.x; acc1.y += a1 * hB.y;
        acc1.z += a1 * hB.z; acc1.w += a1 * hB.w;
        acc2   += p3 * hC;
    }

    float i0 = 1.f / fmaxf(sum0, 1e-16f);
    float i1 = 1.f / fmaxf(sum1, 1e-16f);
    float i2 = 1.f / fmaxf(sum2, 1e-16f);
    float i3 = 1.f / fmaxf(sum3, 1e-16f);
    float sA = h0_is0 ? i0 : i1;
    float sB = h1_is1 ? i1 : (h1_is2 ? i2 : i3);

    float* o = outp + (size_t)node * 288;
    {
        int c = lane * 4;
        float4 b = __ldg((const float4*)(bias + c));
        float4 r;
        r.x = acc0.x * sA + b.x; r.x = (r.x > 0.f) ? r.x : expm1f(r.x);
        r.y = acc0.y * sA + b.y; r.y = (r.y > 0.f) ? r.y : expm1f(r.y);
        r.z = acc0.z * sA + b.z; r.z = (r.z > 0.f) ? r.z : expm1f(r.z);
        r.w = acc0.w * sA + b.w; r.w = (r.w > 0.f) ? r.w : expm1f(r.w);
        *(float4*)(o + c) = r;
    }
    {
        int c = 128 + lane * 4;
        float4 b = __ldg((const float4*)(bias + c));
        float4 r;
        r.x = acc1.x * sB + b.x; r.x = (r.x > 0.f) ? r.x : expm1f(r.x);
        r.y = acc1.y * sB + b.y; r.y = (r.y > 0.f) ? r.y : expm1f(r.y);
        r.z = acc1.z * sB + b.z; r.z = (r.z > 0.f) ? r.z : expm1f(r.z);
        r.w = acc1.w * sB + b.w; r.w = (r.w > 0.f) ? r.w : expm1f(r.w);
        *(float4*)(o + c) = r;
    }
    {
        int c = 256 + lane;
        float v = acc2 * i3 + __ldg(bias + c);
        o[c] = (v > 0.f) ? v : expm1f(v);
    }
}

__global__ void __launch_bounds__(256) k_edge1(
    const float* __restrict__ hfeat, const float* __restrict__ ls,
    const float* __restrict__ ld, const float* __restrict__ bias,
    float* __restrict__ outp)
{
    int node = (blockIdx.x * blockDim.x + threadIdx.x) >> 5;
    if (node >= NN) return;
    int lane = threadIdx.x & 31;
    int s0 = g_rowptr[node], s1 = g_rowptr[node + 1];

    float ldv = __ldg(ld + node);
    float2 acc = make_float2(0.f, 0.f);
    float  acc2 = 0.f;
    float  sum = 0.f;
    bool tail = (lane < 8);

    #pragma unroll 4
    for (int i = s0; i < s1; i++) {
        int s = g_csr[i];                     // warp-uniform
        float v = __ldg(ls + s) + ldv;
        v = fmaxf(v, 0.2f * v);
        float p = __expf(v);
        sum += p;
        const float* hr = hfeat + (size_t)s * 72;
        float2 hA = __ldg((const float2*)hr + lane);       // c = 2*lane
        acc.x += p * hA.x;
        acc.y += p * hA.y;
        if (tail) acc2 += p * __ldg(hr + 64 + lane);
    }

    float inv = 1.f / fmaxf(sum, 1e-16f);
    float* o = outp + (size_t)node * 72;
    {
        int c = lane * 2;
        float bx = __ldg(bias + c), by = __ldg(bias + c + 1);
        float2 r;
        r.x = acc.x * inv + bx; r.x = (r.x > 0.f) ? r.x : expm1f(r.x);
        r.y = acc.y * inv + by; r.y = (r.y > 0.f) ? r.y : expm1f(r.y);
        *(float2*)(o + c) = r;
    }
    if (tail) {
        int c = 64 + lane;
        float v = acc2 * inv + __ldg(bias + c);
        o[c] = (v > 0.f) ? v : expm1f(v);
    }
}

// ----------------------- final residual + score MLP -------------------------
__global__ void __launch_bounds__(256) k_final(
    const float* __restrict__ h3, const float* __restrict__ x0,
    const float* __restrict__ Ws1, const float* __restrict__ bs1,
    const float* __restrict__ Ws2, const float* __restrict__ bs2,
    float* __restrict__ out)
{
    __shared__ float w1s[72 * 32];
    __shared__ float w2s[32];
    __shared__ float b1s[32];
    __shared__ float b2s;
    for (int i = threadIdx.x; i < 72 * 32; i += blockDim.x) w1s[i] = Ws1[i];
    if (threadIdx.x < 32) {
        w2s[threadIdx.x] = Ws2[threadIdx.x];
        b1s[threadIdx.x] = bs1[threadIdx.x];
    }
    if (threadIdx.x == 0) b2s = bs2[0];
    __syncthreads();

    int n = blockIdx.x * blockDim.x + threadIdx.x;
    if (n >= NN) return;
    float t[32];
    #pragma unroll
    for (int j = 0; j < 32; j++) t[j] = b1s[j];
    const float* hr = h3 + (size_t)n * 72;
    const float* xr = x0 + (size_t)n * 72;
    for (int k = 0; k < 72; k++) {
        float v = __ldg(hr + k) + __ldg(xr + k);
        #pragma unroll
        for (int j = 0; j < 32; j += 4) {
            float4 w = *(const float4*)&w1s[k * 32 + j];
            t[j + 0] += v * w.x;
            t[j + 1] += v * w.y;
            t[j + 2] += v * w.z;
            t[j + 3] += v * w.w;
        }
    }
    float s = b2s;
    #pragma unroll
    for (int j = 0; j < 32; j++) s += fmaxf(t[j], 0.f) * w2s[j];
    out[n] = s;
}

// ------------------------------ launch ---------------------------------------
extern "C" void kernel_launch(void* const* d_in, const int* in_sizes, int n_in,
                              void* d_out, int out_size)
{
    const float* x    = (const float*)d_in[0];
    const int*   ei   = (const int*)d_in[1];
    const float* W_in = (const float*)d_in[2];
    const float* b_in = (const float*)d_in[3];
    const float* W1   = (const float*)d_in[4];
    const float* as1  = (const float*)d_in[5];
    const float* ad1  = (const float*)d_in[6];
    const float* b1   = (const float*)d_in[7];
    const float* W2   = (const float*)d_in[8];
    const float* as2  = (const float*)d_in[9];
    const float* ad2  = (const float*)d_in[10];
    const float* b2   = (const float*)d_in[11];
    const float* W3   = (const float*)d_in[12];
    const float* as3  = (const float*)d_in[13];
    const float* ad3  = (const float*)d_in[14];
    const float* b3   = (const float*)d_in[15];
    const float* Ws1  = (const float*)d_in[16];
    const float* bs1  = (const float*)d_in[17];
    const float* Ws2  = (const float*)d_in[18];
    const float* bs2  = (const float*)d_in[19];
    float* out = (float*)d_out;

    float *px0, *ph1, *po1, *ph2, *po2, *ph3, *po3;
    float *pls1, *pld1, *pls2, *pld2, *pls3, *pld3;
    cudaGetSymbolAddress((void**)&px0,  g_x0);
    cudaGetSymbolAddress((void**)&ph1,  g_h1);
    cudaGetSymbolAddress((void**)&po1,  g_o1);
    cudaGetSymbolAddress((void**)&ph2,  g_h2);
    cudaGetSymbolAddress((void**)&po2,  g_o2);
    cudaGetSymbolAddress((void**)&ph3,  g_h3);
    cudaGetSymbolAddress((void**)&po3,  g_o3);
    cudaGetSymbolAddress((void**)&pls1, g_ls1);
    cudaGetSymbolAddress((void**)&pld1, g_ld1);
    cudaGetSymbolAddress((void**)&pls2, g_ls2);
    cudaGetSymbolAddress((void**)&pld2, g_ld2);
    cudaGetSymbolAddress((void**)&pls3, g_ls3);
    cudaGetSymbolAddress((void**)&pld3, g_ld3);

    // CSR build (reused by all three GAT layers)
    k_init_deg<<<(NN + 255) / 256, 256>>>();
    k_count_deg<<<(EE + 255) / 256, 256>>>(ei);
    k_scan_blk<<<NBLK, 256>>>();
    k_scan_top<<<1, 256>>>();
    k_add_self<<<(NN + 255) / 256, 256>>>();
    k_scatter<<<(EE + 255) / 256, 256>>>(ei);

    dim3 g1((NN + 127) / 128, 1);
    dim3 g4((NN + 127) / 128, 4);

    // x0 = x @ W_in + b_in
    k_gemm<<<g1, 256>>>(x, W_in, b_in, px0, NN, IND, 72, 1);

    // layer 1 (4 heads, concat)
    k_gemm<<<g4, 256>>>(px0, W1, nullptr, ph1, NN, 72, 288, 0);
    k_logits4<<<(NN * 4 + 255) / 256, 256>>>(ph1, as1, ad1, pls1, pld1);
    k_edge4<<<(NN * 32) / 256, 256>>>(ph1, pls1, pld1, b1, po1);

    // layer 2 (1 head)
    k_gemm<<<g1, 256>>>(po1, W2, nullptr, ph2, NN, 288, 72, 0);
    k_logits1<<<(NN + 255) / 256, 256>>>(ph2, as2, ad2, pls2, pld2);
    k_edge1<<<(NN * 32) / 256, 256>>>(ph2, pls2, pld2, b2, po2);

    // layer 3 (1 head)
    k_gemm<<<g1, 256>>>(po2, W3, nullptr, ph3, NN, 72, 72, 0);
    k_logits1<<<(NN + 255) / 256, 256>>>(ph3, as3, ad3, pls3, pld3);
    k_edge1<<<(NN * 32) / 256, 256>>>(ph3, pls3, pld3, b3, po3);

    // residual + score MLP
    k_final<<<(NN + 255) / 256, 256>>>(po3, px0, Ws1, bs1, Ws2, bs2, out);
}

// round 4
// speedup vs baseline: 1.1275x; 1.1188x over previous
#include <cuda_runtime.h>
#include <cuda_bf16.h>
#include <math.h>
#include <stdint.h>

#define NN   50000
#define EE   800000
#define ETOT (NN + EE)
#define IND  256
#define HIDD 72
#define NBLK ((NN + 255) / 256)   // 196
#define MPAD 50048                // 391 * 128

// ======================= warp-MMA helpers (baseline PTX) ====================
__device__ __forceinline__ uint32_t smem_to_u32(const void* p) {
    uint32_t a;
    asm("{ .reg .u64 t; cvta.to.shared.u64 t, %1; cvt.u32.u64 %0, t; }" : "=r"(a) : "l"(p));
    return a;
}
__device__ __forceinline__ void ldsm_x4(uint32_t* r, uint32_t addr) {
    asm volatile("ldmatrix.sync.aligned.m8n8.x4.shared.b16 {%0,%1,%2,%3}, [%4];"
        : "=r"(r[0]), "=r"(r[1]), "=r"(r[2]), "=r"(r[3]) : "r"(addr));
}
__device__ __forceinline__ void ldsm_x2(uint32_t* r, uint32_t addr) {
    asm volatile("ldmatrix.sync.aligned.m8n8.x2.shared.b16 {%0,%1}, [%2];"
        : "=r"(r[0]), "=r"(r[1]) : "r"(addr));
}
__device__ __forceinline__ void mma16816(float* c, const uint32_t* a, const uint32_t* b) {
    asm volatile("mma.sync.aligned.m16n8k16.row.col.f32.bf16.bf16.f32 "
        "{%0,%1,%2,%3}, {%4,%5,%6,%7}, {%8,%9}, {%0,%1,%2,%3};"
        : "+f"(c[0]), "+f"(c[1]), "+f"(c[2]), "+f"(c[3])
        : "r"(a[0]), "r"(a[1]), "r"(a[2]), "r"(a[3]), "r"(b[0]), "r"(b[1]));
}

// ------------------------- scratch (device globals) -------------------------
__device__ __align__(16) int   g_rowptr[NN + 1];
__device__ __align__(16) int   g_blksum[NBLK];
__device__ __align__(16) int   g_cursor[NN];
__device__ __align__(16) int   g_csr[ETOT];
__device__ __align__(16) float g_x0[NN * HIDD];
__device__ __align__(16) float g_h1[NN * 288];
__device__ __align__(16) float g_o1[NN * 288];
__device__ __align__(16) float g_h2[NN * HIDD];
__device__ __align__(16) float g_o2[NN * HIDD];
__device__ __align__(16) float g_h3[NN * HIDD];
__device__ __align__(16) float g_o3[NN * HIDD];
__device__ __align__(16) float g_ls1[NN * 4];
__device__ __align__(16) float g_ld1[NN * 4];
__device__ __align__(16) float g_ls2[NN];
__device__ __align__(16) float g_ld2[NN];
__device__ __align__(16) float g_ls3[NN];
__device__ __align__(16) float g_ld3[NN];
// bf16 hi/lo activation buffers (padded rows, K padded to mult of 32)
__device__ __align__(16) __nv_bfloat16 g_xh[(size_t)MPAD * 256];
__device__ __align__(16) __nv_bfloat16 g_xl[(size_t)MPAD * 256];
__device__ __align__(16) __nv_bfloat16 g_x0h[(size_t)MPAD * 128];
__device__ __align__(16) __nv_bfloat16 g_x0l[(size_t)MPAD * 128];
__device__ __align__(16) __nv_bfloat16 g_o1h[(size_t)MPAD * 320];
__device__ __align__(16) __nv_bfloat16 g_o1l[(size_t)MPAD * 320];
__device__ __align__(16) __nv_bfloat16 g_o2h[(size_t)MPAD * 128];
__device__ __align__(16) __nv_bfloat16 g_o2l[(size_t)MPAD * 128];
__device__ __align__(16) __nv_bfloat16 g_wth[288 * 320];
__device__ __align__(16) __nv_bfloat16 g_wtl[288 * 320];

// ------------------------------ CSR build ----------------------------------
__global__ void k_init_deg() {
    int i = blockIdx.x * blockDim.x + threadIdx.x;
    if (i < NN) g_rowptr[i] = 1;
}
__global__ void k_count_deg(const int* __restrict__ ei) {
    int e = blockIdx.x * blockDim.x + threadIdx.x;
    if (e < EE) atomicAdd(&g_rowptr[ei[EE + e]], 1);
}
__global__ void __launch_bounds__(256) k_scan_blk() {
    __shared__ int wsum[8];
    int tid = threadIdx.x, lane = tid & 31, wid = tid >> 5;
    int idx = blockIdx.x * 256 + tid;
    int v = (idx < NN) ? g_rowptr[idx] : 0;
    int x = v;
    #pragma unroll
    for (int o = 1; o < 32; o <<= 1) {
        int y = __shfl_up_sync(0xffffffffu, x, o);
        if (lane >= o) x += y;
    }
    if (lane == 31) wsum[wid] = x;
    __syncthreads();
    if (wid == 0 && lane < 8) {
        int s = wsum[lane];
        #pragma unroll
        for (int o = 1; o < 8; o <<= 1) {
            int y = __shfl_up_sync(0x000000ffu, s, o);
            if (lane >= o) s += y;
        }
        wsum[lane] = s;
    }
    __syncthreads();
    int excl = (wid ? wsum[wid - 1] : 0) + x - v;
    if (idx < NN) g_rowptr[idx] = excl;
    if (tid == 0) g_blksum[blockIdx.x] = wsum[7];
}
__global__ void __launch_bounds__(256) k_scan_top() {
    __shared__ int wsum[8];
    int tid = threadIdx.x, lane = tid & 31, wid = tid >> 5;
    int v = (tid < NBLK) ? g_blksum[tid] : 0;
    int x = v;
    #pragma unroll
    for (int o = 1; o < 32; o <<= 1) {
        int y = __shfl_up_sync(0xffffffffu, x, o);
        if (lane >= o) x += y;
    }
    if (lane == 31) wsum[wid] = x;
    __syncthreads();
    if (wid == 0 && lane < 8) {
        int s = wsum[lane];
        #pragma unroll
        for (int o = 1; o < 8; o <<= 1) {
            int y = __shfl_up_sync(0x000000ffu, s, o);
            if (lane >= o) s += y;
        }
        wsum[lane] = s;
    }
    __syncthreads();
    int excl = (wid ? wsum[wid - 1] : 0) + x - v;
    if (tid < NBLK) g_blksum[tid] = excl;
}
__global__ void k_add_self() {
    int i = blockIdx.x * blockDim.x + threadIdx.x;
    if (i < NN) {
        int r = g_rowptr[i] + g_blksum[i >> 8];
        g_rowptr[i] = r;
        g_csr[r] = i;
        g_cursor[i] = r + 1;
    }
    if (i == 0) g_rowptr[NN] = ETOT;
}
__global__ void k_scatter(const int* __restrict__ ei) {
    int e = blockIdx.x * blockDim.x + threadIdx.x;
    if (e < EE) {
        int s = ei[e];
        int d = ei[EE + e];
        int pos = atomicAdd(&g_cursor[d], 1);
        g_csr[pos] = s;
    }
}

// ----------------------- bf16 hi/lo conversions -----------------------------
__global__ void k_cvt(const float* __restrict__ A, __nv_bfloat16* __restrict__ H,
                      __nv_bfloat16* __restrict__ L, int M, int K, int Kp)
{
    int row = blockIdx.x;
    int c = threadIdx.x * 2;
    float v0 = 0.f, v1 = 0.f;
    if (row < M && c < K) {
        float2 t = *(const float2*)(A + (size_t)row * K + c);
        v0 = t.x; v1 = t.y;
    }
    __nv_bfloat16 h0 = __float2bfloat16(v0);
    __nv_bfloat16 h1 = __float2bfloat16(v1);
    __nv_bfloat16 l0 = __float2bfloat16(v0 - __bfloat162float(h0));
    __nv_bfloat16 l1 = __float2bfloat16(v1 - __bfloat162float(h1));
    size_t o = (size_t)row * Kp + c;
    *(__nv_bfloat162*)(H + o) = __nv_bfloat162(h0, h1);
    *(__nv_bfloat162*)(L + o) = __nv_bfloat162(l0, l1);
}
// W [K,N] fp32 -> Wt hi/lo [N,Kp] bf16 (transposed, zero padded)
__global__ void k_cvtW(const float* __restrict__ W, __nv_bfloat16* __restrict__ H,
                       __nv_bfloat16* __restrict__ L, int K, int N, int Kp)
{
    int idx = blockIdx.x * blockDim.x + threadIdx.x;
    if (idx >= N * Kp) return;
    int n = idx / Kp, k = idx - n * Kp;
    float v = (k < K) ? W[(size_t)k * N + n] : 0.f;
    __nv_bfloat16 h = __float2bfloat16(v);
    H[idx] = h;
    L[idx] = __float2bfloat16(v - __bfloat162float(h));
}

// -------------------- mma.sync GEMM: C[M,KoutTot] = A @ W --------------------
// A hi/lo [MPAD, Kp] bf16 row-major; W transposed hi/lo [KoutTot, Kp] bf16.
// CTA tile 128x72: 12 warps as 4(M) x 3(N); warp tile 32x24 (2x m16, 3x n8).
// bf16 split-3: D += Ah@Bh + Al@Bh + Ah@Bl (fp32 accum).
#define PITCH 40   // bf16 elems per smem row (80B; r*20 mod 32 distinct -> ldsm conflict-free)

__global__ void __launch_bounds__(384)
k_mmagemm(const __nv_bfloat16* __restrict__ Ah, const __nv_bfloat16* __restrict__ Al,
          const __nv_bfloat16* __restrict__ Bh, const __nv_bfloat16* __restrict__ Bl,
          const float* __restrict__ bias, float* __restrict__ C,
          int M, int Kp, int KoutTot, int useBias)
{
    __shared__ __nv_bfloat16 sAh[128 * PITCH];
    __shared__ __nv_bfloat16 sAl[128 * PITCH];
    __shared__ __nv_bfloat16 sBh[72 * PITCH];
    __shared__ __nv_bfloat16 sBl[72 * PITCH];

    int tid = threadIdx.x, wid = tid >> 5, lane = tid & 31;
    int warpM = wid & 3;        // 0..3 -> M offset 32*warpM
    int warpN = wid >> 2;       // 0..2 -> N offset 24*warpN
    int r0 = blockIdx.x * 128;
    int c0 = blockIdx.y * 72;

    float acc[2][3][4];
    #pragma unroll
    for (int mi = 0; mi < 2; mi++)
        #pragma unroll
        for (int ni = 0; ni < 3; ni++)
            #pragma unroll
            for (int q = 0; q < 4; q++) acc[mi][ni][q] = 0.f;

    uint32_t uAh = smem_to_u32(sAh), uAl = smem_to_u32(sAl);
    uint32_t uBh = smem_to_u32(sBh), uBl = smem_to_u32(sBl);

    // ldmatrix lane addressing (bytes)
    int lm = lane >> 3, lj = lane & 7;
    // A: matrix order: (rows0-7,k0-7)(rows8-15,k0-7)(rows0-7,k8-15)(rows8-15,k8-15)
    uint32_t aoffA = (uint32_t)(warpM * 32 + (lm & 1) * 8 + lj) * (PITCH * 2) + (lm >> 1) * 16;
    // B (.x2, lanes 0-15 meaningful): (n0-7,k0-7)(n0-7,k8-15)
    uint32_t aoffB = (uint32_t)(warpN * 24 + lj) * (PITCH * 2) + (lm & 1) * 16;

    for (int kbase = 0; kbase < Kp; kbase += 32) {
        // stage A (128x32) hi+lo
        #pragma unroll 2
        for (int idx = tid; idx < 512; idx += 384) {
            int row = idx >> 2, seg = idx & 3;
            const uint4* ga = (const uint4*)(Ah + (size_t)(r0 + row) * Kp + kbase) + seg;
            *(uint4*)(sAh + row * PITCH + seg * 8) = *ga;
            const uint4* gl = (const uint4*)(Al + (size_t)(r0 + row) * Kp + kbase) + seg;
            *(uint4*)(sAl + row * PITCH + seg * 8) = *gl;
        }
        // stage B (72x32) hi+lo
        for (int idx = tid; idx < 288; idx += 384) {
            int row = idx >> 2, seg = idx & 3;
            *(uint4*)(sBh + row * PITCH + seg * 8) =
                *((const uint4*)(Bh + (size_t)(c0 + row) * Kp + kbase) + seg);
            *(uint4*)(sBl + row * PITCH + seg * 8) =
                *((const uint4*)(Bl + (size_t)(c0 + row) * Kp + kbase) + seg);
        }
        __syncthreads();

        #pragma unroll
        for (int ks = 0; ks < 2; ks++) {
            uint32_t kb = ks * 32;   // byte offset of k16 step
            uint32_t fah[2][4], fal[2][4], fbh[3][2], fbl[3][2];
            #pragma unroll
            for (int mi = 0; mi < 2; mi++) {
                uint32_t off = aoffA + (uint32_t)mi * 16 * (PITCH * 2) + kb;
                ldsm_x4(fah[mi], uAh + off);
                ldsm_x4(fal[mi], uAl + off);
            }
            #pragma unroll
            for (int ni = 0; ni < 3; ni++) {
                uint32_t off = aoffB + (uint32_t)ni * 8 * (PITCH * 2) + kb;
                ldsm_x2(fbh[ni], uBh + off);
                ldsm_x2(fbl[ni], uBl + off);
            }
            #pragma unroll
            for (int mi = 0; mi < 2; mi++)
                #pragma unroll
                for (int ni = 0; ni < 3; ni++) {
                    mma16816(acc[mi][ni], fah[mi], fbh[ni]);
                    mma16816(acc[mi][ni], fal[mi], fbh[ni]);
                    mma16816(acc[mi][ni], fah[mi], fbl[ni]);
                }
        }
        __syncthreads();
    }

    // epilogue: C fragment -> global, optional bias
    int rb = r0 + warpM * 32 + (lane >> 2);
    int cb = c0 + warpN * 24 + (lane & 3) * 2;
    #pragma unroll
    for (int mi = 0; mi < 2; mi++) {
        #pragma unroll
        for (int ni = 0; ni < 3; ni++) {
            int r = rb + mi * 16;
            int c = cb + ni * 8;
            float2 v0 = make_float2(acc[mi][ni][0], acc[mi][ni][1]);
            float2 v1 = make_float2(acc[mi][ni][2], acc[mi][ni][3]);
            if (useBias) {
                float bx = __ldg(bias + c), by = __ldg(bias + c + 1);
                v0.x += bx; v0.y += by;
                v1.x += bx; v1.y += by;
            }
            if (r < M)     *(float2*)(C + (size_t)r * KoutTot + c) = v0;
            if (r + 8 < M) *(float2*)(C + (size_t)(r + 8) * KoutTot + c) = v1;
        }
    }
}

// ------------------------------ logits --------------------------------------
__global__ void k_logits4(const float* __restrict__ h,
                          const float* __restrict__ asrc, const float* __restrict__ adst,
                          float* __restrict__ ls, float* __restrict__ ld)
{
    int t = blockIdx.x * blockDim.x + threadIdx.x;
    if (t >= NN * 4) return;
    int n = t >> 2, hh = t & 3;
    const float* row = h + (size_t)n * 288 + hh * 72;
    const float* av = asrc + hh * 72;
    const float* dv = adst + hh * 72;
    float s = 0.f, d = 0.f;
    #pragma unroll
    for (int c = 0; c < 72; c += 4) {
        float4 r = *(const float4*)(row + c);
        float4 a = __ldg((const float4*)(av + c));
        float4 b = __ldg((const float4*)(dv + c));
        s += r.x * a.x + r.y * a.y + r.z * a.z + r.w * a.w;
        d += r.x * b.x + r.y * b.y + r.z * b.z + r.w * b.w;
    }
    ls[t] = s;
    ld[t] = d;
}
__global__ void k_logits1(const float* __restrict__ h,
                          const float* __restrict__ asrc, const float* __restrict__ adst,
                          float* __restrict__ ls, float* __restrict__ ld)
{
    int n = blockIdx.x * blockDim.x + threadIdx.x;
    if (n >= NN) return;
    const float* row = h + (size_t)n * 72;
    float s = 0.f, d = 0.f;
    #pragma unroll
    for (int c = 0; c < 72; c += 4) {
        float4 r = *(const float4*)(row + c);
        float4 a = __ldg((const float4*)(asrc + c));
        float4 b = __ldg((const float4*)(adst + c));
        s += r.x * a.x + r.y * a.y + r.z * a.z + r.w * a.w;
        d += r.x * b.x + r.y * b.y + r.z * b.z + r.w * b.w;
    }
    ls[n] = s;
    ld[n] = d;
}

// ---------------------- fused GAT edge pass (single sweep) -------------------
__global__ void __launch_bounds__(256) k_edge4(
    const float* __restrict__ hfeat, const float* __restrict__ ls,
    const float* __restrict__ ld, const float* __restrict__ bias,
    float* __restrict__ outp)
{
    int node = (blockIdx.x * blockDim.x + threadIdx.x) >> 5;
    if (node >= NN) return;
    int lane = threadIdx.x & 31;
    int s0 = g_rowptr[node], s1 = g_rowptr[node + 1];

    float4 ldv = __ldg((const float4*)ld + node);

    float4 acc0 = make_float4(0.f, 0.f, 0.f, 0.f);
    float4 acc1 = make_float4(0.f, 0.f, 0.f, 0.f);
    float  acc2 = 0.f;
    float  sum0 = 0.f, sum1 = 0.f, sum2 = 0.f, sum3 = 0.f;

    bool h0_is0 = (lane < 18);
    bool h1_is1 = (lane < 4);
    bool h1_is2 = (lane < 22);

    #pragma unroll 4
    for (int i = s0; i < s1; i++) {
        int s = g_csr[i];
        float4 lv = __ldg((const float4*)ls + s);
        float v0 = lv.x + ldv.x; v0 = fmaxf(v0, 0.2f * v0);
        float v1 = lv.y + ldv.y; v1 = fmaxf(v1, 0.2f * v1);
        float v2 = lv.z + ldv.z; v2 = fmaxf(v2, 0.2f * v2);
        float v3 = lv.w + ldv.w; v3 = fmaxf(v3, 0.2f * v3);
        float p0 = __expf(v0), p1 = __expf(v1);
        float p2 = __expf(v2), p3 = __expf(v3);
        sum0 += p0; sum1 += p1; sum2 += p2; sum3 += p3;

        const float* hr = hfeat + (size_t)s * 288;
        float4 hA = __ldg((const float4*)(hr + lane * 4));
        float4 hB = __ldg((const float4*)(hr + 128 + lane * 4));
        float  hC = __ldg(hr + 256 + lane);

        float a0 = h0_is0 ? p0 : p1;
        float a1 = h1_is1 ? p1 : (h1_is2 ? p2 : p3);
        acc0.x += a0 * hA.x; acc0.y += a0 * hA.y;
        acc0.z += a0 * hA.z; acc0.w += a0 * hA.w;
        acc1.x += a1 * hB.x; acc1.y += a1 * hB.y;
        acc1.z += a1 * hB.z; acc1.w += a1 * hB.w;
        acc2   += p3 * hC;
    }

    float i0 = 1.f / fmaxf(sum0, 1e-16f);
    float i1 = 1.f / fmaxf(sum1, 1e-16f);
    float i2 = 1.f / fmaxf(sum2, 1e-16f);
    float i3 = 1.f / fmaxf(sum3, 1e-16f);
    float sA = h0_is0 ? i0 : i1;
    float sB = h1_is1 ? i1 : (h1_is2 ? i2 : i3);

    float* o = outp + (size_t)node * 288;
    {
        int c = lane * 4;
        float4 b = __ldg((const float4*)(bias + c));
        float4 r;
        r.x = acc0.x * sA + b.x; r.x = (r.x > 0.f) ? r.x : expm1f(r.x);
        r.y = acc0.y * sA + b.y; r.y = (r.y > 0.f) ? r.y : expm1f(r.y);
        r.z = acc0.z * sA + b.z; r.z = (r.z > 0.f) ? r.z : expm1f(r.z);
        r.w = acc0.w * sA + b.w; r.w = (r.w > 0.f) ? r.w : expm1f(r.w);
        *(float4*)(o + c) = r;
    }
    {
        int c = 128 + lane * 4;
        float4 b = __ldg((const float4*)(bias + c));
        float4 r;
        r.x = acc1.x * sB + b.x; r.x = (r.x > 0.f) ? r.x : expm1f(r.x);
        r.y = acc1.y * sB + b.y; r.y = (r.y > 0.f) ? r.y : expm1f(r.y);
        r.z = acc1.z * sB + b.z; r.z = (r.z > 0.f) ? r.z : expm1f(r.z);
        r.w = acc1.w * sB + b.w; r.w = (r.w > 0.f) ? r.w : expm1f(r.w);
        *(float4*)(o + c) = r;
    }
    {
        int c = 256 + lane;
        float v = acc2 * i3 + __ldg(bias + c);
        o[c] = (v > 0.f) ? v : expm1f(v);
    }
}

__global__ void __launch_bounds__(256) k_edge1(
    const float* __restrict__ hfeat, const float* __restrict__ ls,
    const float* __restrict__ ld, const float* __restrict__ bias,
    float* __restrict__ outp)
{
    int node = (blockIdx.x * blockDim.x + threadIdx.x) >> 5;
    if (node >= NN) return;
    int lane = threadIdx.x & 31;
    int s0 = g_rowptr[node], s1 = g_rowptr[node + 1];

    float ldv = __ldg(ld + node);
    float2 acc = make_float2(0.f, 0.f);
    float  acc2 = 0.f;
    float  sum = 0.f;
    bool tail = (lane < 8);

    #pragma unroll 4
    for (int i = s0; i < s1; i++) {
        int s = g_csr[i];
        float v = __ldg(ls + s) + ldv;
        v = fmaxf(v, 0.2f * v);
        float p = __expf(v);
        sum += p;
        const float* hr = hfeat + (size_t)s * 72;
        float2 hA = __ldg((const float2*)hr + lane);
        acc.x += p * hA.x;
        acc.y += p * hA.y;
        if (tail) acc2 += p * __ldg(hr + 64 + lane);
    }

    float inv = 1.f / fmaxf(sum, 1e-16f);
    float* o = outp + (size_t)node * 72;
    {
        int c = lane * 2;
        float bx = __ldg(bias + c), by = __ldg(bias + c + 1);
        float2 r;
        r.x = acc.x * inv + bx; r.x = (r.x > 0.f) ? r.x : expm1f(r.x);
        r.y = acc.y * inv + by; r.y = (r.y > 0.f) ? r.y : expm1f(r.y);
        *(float2*)(o + c) = r;
    }
    if (tail) {
        int c = 64 + lane;
        float v = acc2 * inv + __ldg(bias + c);
        o[c] = (v > 0.f) ? v : expm1f(v);
    }
}

// ----------------------- final residual + score MLP -------------------------
__global__ void __launch_bounds__(256) k_final(
    const float* __restrict__ h3, const float* __restrict__ x0,
    const float* __restrict__ Ws1, const float* __restrict__ bs1,
    const float* __restrict__ Ws2, const float* __restrict__ bs2,
    float* __restrict__ out)
{
    __shared__ float w1s[72 * 32];
    __shared__ float w2s[32];
    __shared__ float b1s[32];
    __shared__ float b2s;
    for (int i = threadIdx.x; i < 72 * 32; i += blockDim.x) w1s[i] = Ws1[i];
    if (threadIdx.x < 32) {
        w2s[threadIdx.x] = Ws2[threadIdx.x];
        b1s[threadIdx.x] = bs1[threadIdx.x];
    }
    if (threadIdx.x == 0) b2s = bs2[0];
    __syncthreads();

    int n = blockIdx.x * blockDim.x + threadIdx.x;
    if (n >= NN) return;
    float t[32];
    #pragma unroll
    for (int j = 0; j < 32; j++) t[j] = b1s[j];
    const float* hr = h3 + (size_t)n * 72;
    const float* xr = x0 + (size_t)n * 72;
    for (int k = 0; k < 72; k++) {
        float v = __ldg(hr + k) + __ldg(xr + k);
        #pragma unroll
        for (int j = 0; j < 32; j += 4) {
            float4 w = *(const float4*)&w1s[k * 32 + j];
            t[j + 0] += v * w.x;
            t[j + 1] += v * w.y;
            t[j + 2] += v * w.z;
            t[j + 3] += v * w.w;
        }
    }
    float s = b2s;
    #pragma unroll
    for (int j = 0; j < 32; j++) s += fmaxf(t[j], 0.f) * w2s[j];
    out[n] = s;
}

// ------------------------------ launch ---------------------------------------
extern "C" void kernel_launch(void* const* d_in, const int* in_sizes, int n_in,
                              void* d_out, int out_size)
{
    const float* x    = (const float*)d_in[0];
    const int*   ei   = (const int*)d_in[1];
    const float* W_in = (const float*)d_in[2];
    const float* b_in = (const float*)d_in[3];
    const float* W1   = (const float*)d_in[4];
    const float* as1  = (const float*)d_in[5];
    const float* ad1  = (const float*)d_in[6];
    const float* b1   = (const float*)d_in[7];
    const float* W2   = (const float*)d_in[8];
    const float* as2  = (const float*)d_in[9];
    const float* ad2  = (const float*)d_in[10];
    const float* b2   = (const float*)d_in[11];
    const float* W3   = (const float*)d_in[12];
    const float* as3  = (const float*)d_in[13];
    const float* ad3  = (const float*)d_in[14];
    const float* b3   = (const float*)d_in[15];
    const float* Ws1  = (const float*)d_in[16];
    const float* bs1  = (const float*)d_in[17];
    const float* Ws2  = (const float*)d_in[18];
    const float* bs2  = (const float*)d_in[19];
    float* out = (float*)d_out;

    float *px0, *ph1, *po1, *ph2, *po2, *ph3, *po3;
    float *pls1, *pld1, *pls2, *pld2, *pls3, *pld3;
    __nv_bfloat16 *pxh, *pxl, *px0h, *px0l, *po1h, *po1l, *po2h, *po2l, *pwth, *pwtl;
    cudaGetSymbolAddress((void**)&px0,  g_x0);
    cudaGetSymbolAddress((void**)&ph1,  g_h1);
    cudaGetSymbolAddress((void**)&po1,  g_o1);
    cudaGetSymbolAddress((void**)&ph2,  g_h2);
    cudaGetSymbolAddress((void**)&po2,  g_o2);
    cudaGetSymbolAddress((void**)&ph3,  g_h3);
    cudaGetSymbolAddress((void**)&po3,  g_o3);
    cudaGetSymbolAddress((void**)&pls1, g_ls1);
    cudaGetSymbolAddress((void**)&pld1, g_ld1);
    cudaGetSymbolAddress((void**)&pls2, g_ls2);
    cudaGetSymbolAddress((void**)&pld2, g_ld2);
    cudaGetSymbolAddress((void**)&pls3, g_ls3);
    cudaGetSymbolAddress((void**)&pld3, g_ld3);
    cudaGetSymbolAddress((void**)&pxh,  g_xh);
    cudaGetSymbolAddress((void**)&pxl,  g_xl);
    cudaGetSymbolAddress((void**)&px0h, g_x0h);
    cudaGetSymbolAddress((void**)&px0l, g_x0l);
    cudaGetSymbolAddress((void**)&po1h, g_o1h);
    cudaGetSymbolAddress((void**)&po1l, g_o1l);
    cudaGetSymbolAddress((void**)&po2h, g_o2h);
    cudaGetSymbolAddress((void**)&po2l, g_o2l);
    cudaGetSymbolAddress((void**)&pwth, g_wth);
    cudaGetSymbolAddress((void**)&pwtl, g_wtl);

    // --- layer 0 prep + CSR begin (profiled capture slot 3 = GEMM) ---
    k_cvt<<<MPAD, 128>>>(x, pxh, pxl, NN, 256, 256);                          // 0
    k_cvtW<<<(72 * 256 + 255) / 256, 256>>>(W_in, pwth, pwtl, 256, 72, 256);  // 1
    k_init_deg<<<(NN + 255) / 256, 256>>>();                                  // 2
    k_mmagemm<<<dim3(391, 1), 384>>>(pxh, pxl, pwth, pwtl,
                                     b_in, px0, NN, 256, 72, 1);              // 3 (profiled)
    k_count_deg<<<(EE + 255) / 256, 256>>>(ei);
    k_scan_blk<<<NBLK, 256>>>();
    k_scan_top<<<1, 256>>>();
    k_add_self<<<(NN + 255) / 256, 256>>>();
    k_scatter<<<(EE + 255) / 256, 256>>>(ei);

    // --- layer 1 (4 heads, concat) ---
    k_cvt<<<MPAD, 64>>>(px0, px0h, px0l, NN, 72, 128);
    k_cvtW<<<(288 * 128 + 255) / 256, 256>>>(W1, pwth, pwtl, 72, 288, 128);
    k_mmagemm<<<dim3(391, 4), 384>>>(px0h, px0l, pwth, pwtl,
                                     nullptr, ph1, NN, 128, 288, 0);
    k_logits4<<<(NN * 4 + 255) / 256, 256>>>(ph1, as1, ad1, pls1, pld1);
    k_edge4<<<(NN * 32) / 256, 256>>>(ph1, pls1, pld1, b1, po1);

    // --- layer 2 (1 head) ---
    k_cvt<<<MPAD, 160>>>(po1, po1h, po1l, NN, 288, 320);
    k_cvtW<<<(72 * 320 + 255) / 256, 256>>>(W2, pwth, pwtl, 288, 72, 320);
    k_mmagemm<<<dim3(391, 1), 384>>>(po1h, po1l, pwth, pwtl,
                                     nullptr, ph2, NN, 320, 72, 0);
    k_logits1<<<(NN + 255) / 256, 256>>>(ph2, as2, ad2, pls2, pld2);
    k_edge1<<<(NN * 32) / 256, 256>>>(ph2, pls2, pld2, b2, po2);

    // --- layer 3 (1 head) ---
    k_cvt<<<MPAD, 64>>>(po2, po2h, po2l, NN, 72, 128);
    k_cvtW<<<(72 * 128 + 255) / 256, 256>>>(W3, pwth, pwtl, 72, 72, 128);
    k_mmagemm<<<dim3(391, 1), 384>>>(po2h, po2l, pwth, pwtl,
                                     nullptr, ph3, NN, 128, 72, 0);
    k_logits1<<<(NN + 255) / 256, 256>>>(ph3, as3, ad3, pls3, pld3);
    k_edge1<<<(NN * 32) / 256, 256>>>(ph3, pls3, pld3, b3, po3);

    // --- residual + score MLP ---
    k_final<<<(NN + 255) / 256, 256>>>(po3, px0, Ws1, bs1, Ws2, bs2, out);
}

// round 5
// speedup vs baseline: 1.3377x; 1.1864x over previous
#include <cuda_runtime.h>
#include <cuda_bf16.h>
#include <math.h>
#include <stdint.h>

#define NN   50000
#define EE   800000
#define ETOT (NN + EE)
#define IND  256
#define HIDD 72
#define NBLK ((NN + 255) / 256)   // 196

// ======================= warp-MMA helpers (baseline PTX) ====================
__device__ __forceinline__ uint32_t smem_to_u32(const void* p) {
    uint32_t a;
    asm("{ .reg .u64 t; cvta.to.shared.u64 t, %1; cvt.u32.u64 %0, t; }" : "=r"(a) : "l"(p));
    return a;
}
__device__ __forceinline__ void ldsm_x4(uint32_t* r, uint32_t addr) {
    asm volatile("ldmatrix.sync.aligned.m8n8.x4.shared.b16 {%0,%1,%2,%3}, [%4];"
        : "=r"(r[0]), "=r"(r[1]), "=r"(r[2]), "=r"(r[3]) : "r"(addr));
}
__device__ __forceinline__ void ldsm_x2(uint32_t* r, uint32_t addr) {
    asm volatile("ldmatrix.sync.aligned.m8n8.x2.shared.b16 {%0,%1}, [%2];"
        : "=r"(r[0]), "=r"(r[1]) : "r"(addr));
}
__device__ __forceinline__ void mma16816(float* c, const uint32_t* a, const uint32_t* b) {
    asm volatile("mma.sync.aligned.m16n8k16.row.col.f32.bf16.bf16.f32 "
        "{%0,%1,%2,%3}, {%4,%5,%6,%7}, {%8,%9}, {%0,%1,%2,%3};"
        : "+f"(c[0]), "+f"(c[1]), "+f"(c[2]), "+f"(c[3])
        : "r"(a[0]), "r"(a[1]), "r"(a[2]), "r"(a[3]), "r"(b[0]), "r"(b[1]));
}

// ------------------------- scratch (device globals) -------------------------
__device__ __align__(16) int   g_rowptr[NN + 1];
__device__ __align__(16) int   g_blksum[NBLK];
__device__ __align__(16) int   g_cursor[NN];
__device__ __align__(16) int   g_csr[ETOT];
__device__ __align__(16) float g_x0[NN * HIDD];
__device__ __align__(16) float g_h1[NN * 288];
__device__ __align__(16) float g_o1[NN * 288];
__device__ __align__(16) float g_h2[NN * HIDD];
__device__ __align__(16) float g_o2[NN * HIDD];
__device__ __align__(16) float g_h3[NN * HIDD];
__device__ __align__(16) float g_o3[NN * HIDD];
__device__ __align__(16) float g_ls1[NN * 4];
__device__ __align__(16) float g_ld1[NN * 4];
__device__ __align__(16) float g_ls2[NN];
__device__ __align__(16) float g_ld2[NN];
__device__ __align__(16) float g_ls3[NN];
__device__ __align__(16) float g_ld3[NN];
// transposed hi/lo weights [N, Kp] (max 288*320)
__device__ __align__(16) __nv_bfloat16 g_wth[288 * 320];
__device__ __align__(16) __nv_bfloat16 g_wtl[288 * 320];

// ------------------------------ CSR build ----------------------------------
__global__ void k_init_deg() {
    int i = blockIdx.x * blockDim.x + threadIdx.x;
    if (i < NN) g_rowptr[i] = 1;
}
__global__ void k_count_deg(const int* __restrict__ ei) {
    int e = blockIdx.x * blockDim.x + threadIdx.x;
    if (e < EE) atomicAdd(&g_rowptr[ei[EE + e]], 1);
}
__global__ void __launch_bounds__(256) k_scan_blk() {
    __shared__ int wsum[8];
    int tid = threadIdx.x, lane = tid & 31, wid = tid >> 5;
    int idx = blockIdx.x * 256 + tid;
    int v = (idx < NN) ? g_rowptr[idx] : 0;
    int x = v;
    #pragma unroll
    for (int o = 1; o < 32; o <<= 1) {
        int y = __shfl_up_sync(0xffffffffu, x, o);
        if (lane >= o) x += y;
    }
    if (lane == 31) wsum[wid] = x;
    __syncthreads();
    if (wid == 0 && lane < 8) {
        int s = wsum[lane];
        #pragma unroll
        for (int o = 1; o < 8; o <<= 1) {
            int y = __shfl_up_sync(0x000000ffu, s, o);
            if (lane >= o) s += y;
        }
        wsum[lane] = s;
    }
    __syncthreads();
    int excl = (wid ? wsum[wid - 1] : 0) + x - v;
    if (idx < NN) g_rowptr[idx] = excl;
    if (tid == 0) g_blksum[blockIdx.x] = wsum[7];
}
__global__ void __launch_bounds__(256) k_scan_top() {
    __shared__ int wsum[8];
    int tid = threadIdx.x, lane = tid & 31, wid = tid >> 5;
    int v = (tid < NBLK) ? g_blksum[tid] : 0;
    int x = v;
    #pragma unroll
    for (int o = 1; o < 32; o <<= 1) {
        int y = __shfl_up_sync(0xffffffffu, x, o);
        if (lane >= o) x += y;
    }
    if (lane == 31) wsum[wid] = x;
    __syncthreads();
    if (wid == 0 && lane < 8) {
        int s = wsum[lane];
        #pragma unroll
        for (int o = 1; o < 8; o <<= 1) {
            int y = __shfl_up_sync(0x000000ffu, s, o);
            if (lane >= o) s += y;
        }
        wsum[lane] = s;
    }
    __syncthreads();
    int excl = (wid ? wsum[wid - 1] : 0) + x - v;
    if (tid < NBLK) g_blksum[tid] = excl;
}
__global__ void k_add_self() {
    int i = blockIdx.x * blockDim.x + threadIdx.x;
    if (i < NN) {
        int r = g_rowptr[i] + g_blksum[i >> 8];
        g_rowptr[i] = r;
        g_csr[r] = i;
        g_cursor[i] = r + 1;
    }
    if (i == 0) g_rowptr[NN] = ETOT;
}
__global__ void k_scatter(const int* __restrict__ ei) {
    int e = blockIdx.x * blockDim.x + threadIdx.x;
    if (e < EE) {
        int s = ei[e];
        int d = ei[EE + e];
        int pos = atomicAdd(&g_cursor[d], 1);
        g_csr[pos] = s;
    }
}

// ----------------- W [K,N] fp32 -> Wt hi/lo [N,Kp] bf16 (tiny) ---------------
__global__ void k_cvtW(const float* __restrict__ W, __nv_bfloat16* __restrict__ H,
                       __nv_bfloat16* __restrict__ L, int K, int N, int Kp)
{
    int idx = blockIdx.x * blockDim.x + threadIdx.x;
    if (idx >= N * Kp) return;
    int n = idx / Kp, k = idx - n * Kp;
    float v = (k < K) ? W[(size_t)k * N + n] : 0.f;
    __nv_bfloat16 h = __float2bfloat16(v);
    H[idx] = h;
    L[idx] = __float2bfloat16(v - __bfloat162float(h));
}

// -------------------- mma.sync GEMM: C[M,KoutTot] = A @ W --------------------
// A fp32 [M,Kin] row-major, split to hi/lo bf16 in the staging loop.
// W transposed hi/lo [KoutTot, Kp] bf16 global.
// CTA tile 128x72: 12 warps = 4(M) x 3(N); warp tile 32x24.
// bf16 split-3: D += Ah@Bh + Al@Bh + Ah@Bl (fp32 accum).
// Optional fused attention logits: ls/ld[gr*lstride + blockIdx.y] = h . a_{src,dst}
#define PITCH 40   // bf16 per smem row (80B; conflict-free for ldmatrix)

__global__ void __launch_bounds__(384)
k_mmagemm(const float* __restrict__ A,
          const __nv_bfloat16* __restrict__ Bh, const __nv_bfloat16* __restrict__ Bl,
          const float* __restrict__ bias, float* __restrict__ C,
          const float* __restrict__ asrc, const float* __restrict__ adst,
          float* __restrict__ ls, float* __restrict__ ld, int lstride,
          int M, int Kin, int KoutTot, int useBias)
{
    __shared__ __nv_bfloat16 sAh[128 * PITCH];
    __shared__ __nv_bfloat16 sAl[128 * PITCH];
    __shared__ __nv_bfloat16 sBh[72 * PITCH];
    __shared__ __nv_bfloat16 sBl[72 * PITCH];
    __shared__ float sLs[128];
    __shared__ float sLd[128];

    int tid = threadIdx.x, wid = tid >> 5, lane = tid & 31;
    int warpM = wid & 3;
    int warpN = wid >> 2;
    int r0 = blockIdx.x * 128;
    int c0 = blockIdx.y * 72;
    int Kp = (Kin + 31) & ~31;

    float acc[2][3][4];
    #pragma unroll
    for (int mi = 0; mi < 2; mi++)
        #pragma unroll
        for (int ni = 0; ni < 3; ni++)
            #pragma unroll
            for (int q = 0; q < 4; q++) acc[mi][ni][q] = 0.f;

    uint32_t uAh = smem_to_u32(sAh), uAl = smem_to_u32(sAl);
    uint32_t uBh = smem_to_u32(sBh), uBl = smem_to_u32(sBl);

    int lm = lane >> 3, lj = lane & 7;
    uint32_t aoffA = (uint32_t)(warpM * 32 + (lm & 1) * 8 + lj) * (PITCH * 2) + (lm >> 1) * 16;
    uint32_t aoffB = (uint32_t)(warpN * 24 + lj) * (PITCH * 2) + (lm & 1) * 16;

    for (int kbase = 0; kbase < Kp; kbase += 32) {
        // stage A: 128 rows x 32 cols fp32 -> hi/lo bf16 (1024 float4 groups)
        #pragma unroll 3
        for (int idx = tid; idx < 1024; idx += 384) {
            int row = idx >> 3, seg = idx & 7;
            int gr = r0 + row;
            int gc = kbase + seg * 4;
            float4 v = make_float4(0.f, 0.f, 0.f, 0.f);
            if (gr < M) {
                const float* ap = A + (size_t)gr * Kin;
                if (gc + 3 < Kin) v = *(const float4*)(ap + gc);
                else {
                    if (gc + 0 < Kin) v.x = ap[gc + 0];
                    if (gc + 1 < Kin) v.y = ap[gc + 1];
                    if (gc + 2 < Kin) v.z = ap[gc + 2];
                    if (gc + 3 < Kin) v.w = ap[gc + 3];
                }
            }
            __nv_bfloat16 hx = __float2bfloat16(v.x), hy = __float2bfloat16(v.y);
            __nv_bfloat16 hz = __float2bfloat16(v.z), hw = __float2bfloat16(v.w);
            __nv_bfloat162 h01(hx, hy), h23(hz, hw);
            __nv_bfloat162 l01(__float2bfloat16(v.x - __bfloat162float(hx)),
                               __float2bfloat16(v.y - __bfloat162float(hy)));
            __nv_bfloat162 l23(__float2bfloat16(v.z - __bfloat162float(hz)),
                               __float2bfloat16(v.w - __bfloat162float(hw)));
            __nv_bfloat162* ph = (__nv_bfloat162*)(sAh + row * PITCH + seg * 4);
            ph[0] = h01; ph[1] = h23;
            __nv_bfloat162* pl = (__nv_bfloat162*)(sAl + row * PITCH + seg * 4);
            pl[0] = l01; pl[1] = l23;
        }
        // stage B: 72 rows x 32 cols bf16 hi+lo (288 uint4 groups)
        for (int idx = tid; idx < 288; idx += 384) {
            int row = idx >> 2, seg = idx & 3;
            *(uint4*)(sBh + row * PITCH + seg * 8) =
                *((const uint4*)(Bh + (size_t)(c0 + row) * Kp + kbase) + seg);
            *(uint4*)(sBl + row * PITCH + seg * 8) =
                *((const uint4*)(Bl + (size_t)(c0 + row) * Kp + kbase) + seg);
        }
        __syncthreads();

        #pragma unroll
        for (int ks = 0; ks < 2; ks++) {
            uint32_t kb = ks * 32;
            uint32_t fah[2][4], fal[2][4], fbh[3][2], fbl[3][2];
            #pragma unroll
            for (int mi = 0; mi < 2; mi++) {
                uint32_t off = aoffA + (uint32_t)mi * 16 * (PITCH * 2) + kb;
                ldsm_x4(fah[mi], uAh + off);
                ldsm_x4(fal[mi], uAl + off);
            }
            #pragma unroll
            for (int ni = 0; ni < 3; ni++) {
                uint32_t off = aoffB + (uint32_t)ni * 8 * (PITCH * 2) + kb;
                ldsm_x2(fbh[ni], uBh + off);
                ldsm_x2(fbl[ni], uBl + off);
            }
            #pragma unroll
            for (int mi = 0; mi < 2; mi++)
                #pragma unroll
                for (int ni = 0; ni < 3; ni++) {
                    mma16816(acc[mi][ni], fah[mi], fbh[ni]);
                    mma16816(acc[mi][ni], fal[mi], fbh[ni]);
                    mma16816(acc[mi][ni], fah[mi], fbl[ni]);
                }
        }
        __syncthreads();
    }

    // ---- store C (+bias) ----
    int rb = r0 + warpM * 32 + (lane >> 2);
    int cb = c0 + warpN * 24 + (lane & 3) * 2;
    #pragma unroll
    for (int mi = 0; mi < 2; mi++) {
        #pragma unroll
        for (int ni = 0; ni < 3; ni++) {
            int r = rb + mi * 16;
            int c = cb + ni * 8;
            float2 v0 = make_float2(acc[mi][ni][0], acc[mi][ni][1]);
            float2 v1 = make_float2(acc[mi][ni][2], acc[mi][ni][3]);
            if (useBias) {
                float bx = __ldg(bias + c), by = __ldg(bias + c + 1);
                v0.x += bx; v0.y += by;
                v1.x += bx; v1.y += by;
            }
            if (r < M)     *(float2*)(C + (size_t)r * KoutTot + c) = v0;
            if (r + 8 < M) *(float2*)(C + (size_t)(r + 8) * KoutTot + c) = v1;
        }
    }

    // ---- fused attention logits: per-row dot with a_src / a_dst ----
    if (ls != nullptr) {
        const float* av = asrc + blockIdx.y * 72;
        const float* dv = adst + blockIdx.y * 72;
        float as6[6], ad6[6];
        #pragma unroll
        for (int t6 = 0; t6 < 6; t6++) {
            int ni = t6 >> 1, j = t6 & 1;
            int cc = warpN * 24 + ni * 8 + (lane & 3) * 2 + j;
            as6[t6] = __ldg(av + cc);
            ad6[t6] = __ldg(dv + cc);
        }
        float sp[4], dp[4];
        #pragma unroll
        for (int mi = 0; mi < 2; mi++)
            #pragma unroll
            for (int half = 0; half < 2; half++) {
                float s = 0.f, d = 0.f;
                #pragma unroll
                for (int ni = 0; ni < 3; ni++) {
                    s += acc[mi][ni][half * 2 + 0] * as6[ni * 2 + 0];
                    s += acc[mi][ni][half * 2 + 1] * as6[ni * 2 + 1];
                    d += acc[mi][ni][half * 2 + 0] * ad6[ni * 2 + 0];
                    d += acc[mi][ni][half * 2 + 1] * ad6[ni * 2 + 1];
                }
                sp[mi * 2 + half] = s;
                dp[mi * 2 + half] = d;
            }
        #pragma unroll
        for (int k = 0; k < 4; k++) {
            #pragma unroll
            for (int o = 1; o < 4; o <<= 1) {
                sp[k] += __shfl_xor_sync(0xffffffffu, sp[k], o);
                dp[k] += __shfl_xor_sync(0xffffffffu, dp[k], o);
            }
        }
        if (tid < 128) { sLs[tid] = 0.f; sLd[tid] = 0.f; }
        __syncthreads();
        if ((lane & 3) == 0) {
            int rloc = warpM * 32 + (lane >> 2);
            atomicAdd(&sLs[rloc],      sp[0]); atomicAdd(&sLd[rloc],      dp[0]);
            atomicAdd(&sLs[rloc + 8],  sp[1]); atomicAdd(&sLd[rloc + 8],  dp[1]);
            atomicAdd(&sLs[rloc + 16], sp[2]); atomicAdd(&sLd[rloc + 16], dp[2]);
            atomicAdd(&sLs[rloc + 24], sp[3]); atomicAdd(&sLd[rloc + 24], dp[3]);
        }
        __syncthreads();
        if (tid < 128) {
            int gr = r0 + tid;
            if (gr < M) {
                ls[(size_t)gr * lstride + blockIdx.y] = sLs[tid];
                ld[(size_t)gr * lstride + blockIdx.y] = sLd[tid];
            }
        }
    }
}

// ---------------------- fused GAT edge pass (single sweep) -------------------
__global__ void __launch_bounds__(256) k_edge4(
    const float* __restrict__ hfeat, const float* __restrict__ ls,
    const float* __restrict__ ld, const float* __restrict__ bias,
    float* __restrict__ outp)
{
    int node = (blockIdx.x * blockDim.x + threadIdx.x) >> 5;
    if (node >= NN) return;
    int lane = threadIdx.x & 31;
    int s0 = g_rowptr[node], s1 = g_rowptr[node + 1];

    float4 ldv = __ldg((const float4*)ld + node);

    float4 acc0 = make_float4(0.f, 0.f, 0.f, 0.f);
    float4 acc1 = make_float4(0.f, 0.f, 0.f, 0.f);
    float  acc2 = 0.f;
    float  sum0 = 0.f, sum1 = 0.f, sum2 = 0.f, sum3 = 0.f;

    bool h0_is0 = (lane < 18);
    bool h1_is1 = (lane < 4);
    bool h1_is2 = (lane < 22);

    #pragma unroll 4
    for (int i = s0; i < s1; i++) {
        int s = g_csr[i];
        float4 lv = __ldg((const float4*)ls + s);
        float v0 = lv.x + ldv.x; v0 = fmaxf(v0, 0.2f * v0);
        float v1 = lv.y + ldv.y; v1 = fmaxf(v1, 0.2f * v1);
        float v2 = lv.z + ldv.z; v2 = fmaxf(v2, 0.2f * v2);
        float v3 = lv.w + ldv.w; v3 = fmaxf(v3, 0.2f * v3);
        float p0 = __expf(v0), p1 = __expf(v1);
        float p2 = __expf(v2), p3 = __expf(v3);
        sum0 += p0; sum1 += p1; sum2 += p2; sum3 += p3;

        const float* hr = hfeat + (size_t)s * 288;
        float4 hA = __ldg((const float4*)(hr + lane * 4));
        float4 hB = __ldg((const float4*)(hr + 128 + lane * 4));
        float  hC = __ldg(hr + 256 + lane);

        float a0 = h0_is0 ? p0 : p1;
        float a1 = h1_is1 ? p1 : (h1_is2 ? p2 : p3);
        acc0.x += a0 * hA.x; acc0.y += a0 * hA.y;
        acc0.z += a0 * hA.z; acc0.w += a0 * hA.w;
        acc1.x += a1 * hB.x; acc1.y += a1 * hB.y;
        acc1.z += a1 * hB.z; acc1.w += a1 * hB.w;
        acc2   += p3 * hC;
    }

    float i0 = 1.f / fmaxf(sum0, 1e-16f);
    float i1 = 1.f / fmaxf(sum1, 1e-16f);
    float i2 = 1.f / fmaxf(sum2, 1e-16f);
    float i3 = 1.f / fmaxf(sum3, 1e-16f);
    float sA = h0_is0 ? i0 : i1;
    float sB = h1_is1 ? i1 : (h1_is2 ? i2 : i3);

    float* o = outp + (size_t)node * 288;
    {
        int c = lane * 4;
        float4 b = __ldg((const float4*)(bias + c));
        float4 r;
        r.x = acc0.x * sA + b.x; r.x = (r.x > 0.f) ? r.x : expm1f(r.x);
        r.y = acc0.y * sA + b.y; r.y = (r.y > 0.f) ? r.y : expm1f(r.y);
        r.z = acc0.z * sA + b.z; r.z = (r.z > 0.f) ? r.z : expm1f(r.z);
        r.w = acc0.w * sA + b.w; r.w = (r.w > 0.f) ? r.w : expm1f(r.w);
        *(float4*)(o + c) = r;
    }
    {
        int c = 128 + lane * 4;
        float4 b = __ldg((const float4*)(bias + c));
        float4 r;
        r.x = acc1.x * sB + b.x; r.x = (r.x > 0.f) ? r.x : expm1f(r.x);
        r.y = acc1.y * sB + b.y; r.y = (r.y > 0.f) ? r.y : expm1f(r.y);
        r.z = acc1.z * sB + b.z; r.z = (r.z > 0.f) ? r.z : expm1f(r.z);
        r.w = acc1.w * sB + b.w; r.w = (r.w > 0.f) ? r.w : expm1f(r.w);
        *(float4*)(o + c) = r;
    }
    {
        int c = 256 + lane;
        float v = acc2 * i3 + __ldg(bias + c);
        o[c] = (v > 0.f) ? v : expm1f(v);
    }
}

__global__ void __launch_bounds__(256) k_edge1(
    const float* __restrict__ hfeat, const float* __restrict__ ls,
    const float* __restrict__ ld, const float* __restrict__ bias,
    float* __restrict__ outp)
{
    int node = (blockIdx.x * blockDim.x + threadIdx.x) >> 5;
    if (node >= NN) return;
    int lane = threadIdx.x & 31;
    int s0 = g_rowptr[node], s1 = g_rowptr[node + 1];

    float ldv = __ldg(ld + node);
    float2 acc = make_float2(0.f, 0.f);
    float  acc2 = 0.f;
    float  sum = 0.f;
    bool tail = (lane < 8);

    #pragma unroll 4
    for (int i = s0; i < s1; i++) {
        int s = g_csr[i];
        float v = __ldg(ls + s) + ldv;
        v = fmaxf(v, 0.2f * v);
        float p = __expf(v);
        sum += p;
        const float* hr = hfeat + (size_t)s * 72;
        float2 hA = __ldg((const float2*)hr + lane);
        acc.x += p * hA.x;
        acc.y += p * hA.y;
        if (tail) acc2 += p * __ldg(hr + 64 + lane);
    }

    float inv = 1.f / fmaxf(sum, 1e-16f);
    float* o = outp + (size_t)node * 72;
    {
        int c = lane * 2;
        float bx = __ldg(bias + c), by = __ldg(bias + c + 1);
        float2 r;
        r.x = acc.x * inv + bx; r.x = (r.x > 0.f) ? r.x : expm1f(r.x);
        r.y = acc.y * inv + by; r.y = (r.y > 0.f) ? r.y : expm1f(r.y);
        *(float2*)(o + c) = r;
    }
    if (tail) {
        int c = 64 + lane;
        float v = acc2 * inv + __ldg(bias + c);
        o[c] = (v > 0.f) ? v : expm1f(v);
    }
}

// ----------------------- final residual + score MLP -------------------------
__global__ void __launch_bounds__(256) k_final(
    const float* __restrict__ h3, const float* __restrict__ x0,
    const float* __restrict__ Ws1, const float* __restrict__ bs1,
    const float* __restrict__ Ws2, const float* __restrict__ bs2,
    float* __restrict__ out)
{
    __shared__ float w1s[72 * 32];
    __shared__ float w2s[32];
    __shared__ float b1s[32];
    __shared__ float b2s;
    for (int i = threadIdx.x; i < 72 * 32; i += blockDim.x) w1s[i] = Ws1[i];
    if (threadIdx.x < 32) {
        w2s[threadIdx.x] = Ws2[threadIdx.x];
        b1s[threadIdx.x] = bs1[threadIdx.x];
    }
    if (threadIdx.x == 0) b2s = bs2[0];
    __syncthreads();

    int n = blockIdx.x * blockDim.x + threadIdx.x;
    if (n >= NN) return;
    float t[32];
    #pragma unroll
    for (int j = 0; j < 32; j++) t[j] = b1s[j];
    const float* hr = h3 + (size_t)n * 72;
    const float* xr = x0 + (size_t)n * 72;
    for (int k = 0; k < 72; k++) {
        float v = __ldg(hr + k) + __ldg(xr + k);
        #pragma unroll
        for (int j = 0; j < 32; j += 4) {
            float4 w = *(const float4*)&w1s[k * 32 + j];
            t[j + 0] += v * w.x;
            t[j + 1] += v * w.y;
            t[j + 2] += v * w.z;
            t[j + 3] += v * w.w;
        }
    }
    float s = b2s;
    #pragma unroll
    for (int j = 0; j < 32; j++) s += fmaxf(t[j], 0.f) * w2s[j];
    out[n] = s;
}

// ------------------------------ launch ---------------------------------------
extern "C" void kernel_launch(void* const* d_in, const int* in_sizes, int n_in,
                              void* d_out, int out_size)
{
    const float* x    = (const float*)d_in[0];
    const int*   ei   = (const int*)d_in[1];
    const float* W_in = (const float*)d_in[2];
    const float* b_in = (const float*)d_in[3];
    const float* W1   = (const float*)d_in[4];
    const float* as1  = (const float*)d_in[5];
    const float* ad1  = (const float*)d_in[6];
    const float* b1   = (const float*)d_in[7];
    const float* W2   = (const float*)d_in[8];
    const float* as2  = (const float*)d_in[9];
    const float* ad2  = (const float*)d_in[10];
    const float* b2   = (const float*)d_in[11];
    const float* W3   = (const float*)d_in[12];
    const float* as3  = (const float*)d_in[13];
    const float* ad3  = (const float*)d_in[14];
    const float* b3   = (const float*)d_in[15];
    const float* Ws1  = (const float*)d_in[16];
    const float* bs1  = (const float*)d_in[17];
    const float* Ws2  = (const float*)d_in[18];
    const float* bs2  = (const float*)d_in[19];
    float* out = (float*)d_out;

    float *px0, *ph1, *po1, *ph2, *po2, *ph3, *po3;
    float *pls1, *pld1, *pls2, *pld2, *pls3, *pld3;
    __nv_bfloat16 *pwth, *pwtl;
    cudaGetSymbolAddress((void**)&px0,  g_x0);
    cudaGetSymbolAddress((void**)&ph1,  g_h1);
    cudaGetSymbolAddress((void**)&po1,  g_o1);
    cudaGetSymbolAddress((void**)&ph2,  g_h2);
    cudaGetSymbolAddress((void**)&po2,  g_o2);
    cudaGetSymbolAddress((void**)&ph3,  g_h3);
    cudaGetSymbolAddress((void**)&po3,  g_o3);
    cudaGetSymbolAddress((void**)&pls1, g_ls1);
    cudaGetSymbolAddress((void**)&pld1, g_ld1);
    cudaGetSymbolAddress((void**)&pls2, g_ls2);
    cudaGetSymbolAddress((void**)&pld2, g_ld2);
    cudaGetSymbolAddress((void**)&pls3, g_ls3);
    cudaGetSymbolAddress((void**)&pld3, g_ld3);
    cudaGetSymbolAddress((void**)&pwth, g_wth);
    cudaGetSymbolAddress((void**)&pwtl, g_wtl);

    // --- layer 0 + CSR begin (profiled capture slot 3 = gemm0) ---
    k_cvtW<<<(72 * 256 + 255) / 256, 256>>>(W_in, pwth, pwtl, 256, 72, 256);  // 0
    k_init_deg<<<(NN + 255) / 256, 256>>>();                                  // 1
    k_count_deg<<<(EE + 255) / 256, 256>>>(ei);                               // 2
    k_mmagemm<<<dim3(391, 1), 384>>>(x, pwth, pwtl, b_in, px0,
                                     nullptr, nullptr, nullptr, nullptr, 1,
                                     NN, 256, 72, 1);                         // 3 (profiled)
    k_scan_blk<<<NBLK, 256>>>();
    k_scan_top<<<1, 256>>>();
    k_add_self<<<(NN + 255) / 256, 256>>>();
    k_scatter<<<(EE + 255) / 256, 256>>>(ei);

    // --- layer 1 (4 heads, concat; logits fused into GEMM epilogue) ---
    k_cvtW<<<(288 * 96 + 255) / 256, 256>>>(W1, pwth, pwtl, 72, 288, 96);
    k_mmagemm<<<dim3(391, 4), 384>>>(px0, pwth, pwtl, nullptr, ph1,
                                     as1, ad1, pls1, pld1, 4,
                                     NN, 72, 288, 0);
    k_edge4<<<(NN * 32) / 256, 256>>>(ph1, pls1, pld1, b1, po1);

    // --- layer 2 (1 head) ---
    k_cvtW<<<(72 * 288 + 255) / 256, 256>>>(W2, pwth, pwtl, 288, 72, 288);
    k_mmagemm<<<dim3(391, 1), 384>>>(po1, pwth, pwtl, nullptr, ph2,
                                     as2, ad2, pls2, pld2, 1,
                                     NN, 288, 72, 0);
    k_edge1<<<(NN * 32) / 256, 256>>>(ph2, pls2, pld2, b2, po2);

    // --- layer 3 (1 head) ---
    k_cvtW<<<(72 * 96 + 255) / 256, 256>>>(W3, pwth, pwtl, 72, 72, 96);
    k_mmagemm<<<dim3(391, 1), 384>>>(po2, pwth, pwtl, nullptr, ph3,
                                     as3, ad3, pls3, pld3, 1,
                                     NN, 72, 72, 0);
    k_edge1<<<(NN * 32) / 256, 256>>>(ph3, pls3, pld3, b3, po3);

    // --- residual + score MLP ---
    k_final<<<(NN + 255) / 256, 256>>>(po3, px0, Ws1, bs1, Ws2, bs2, out);
}

// round 6
// speedup vs baseline: 1.3967x; 1.0441x over previous
#include <cuda_runtime.h>
#include <cuda_bf16.h>
#include <math.h>
#include <stdint.h>

#define NN   50000
#define EE   800000
#define ETOT (NN + EE)
#define IND  256
#define HIDD 72
#define NBLK ((NN + 255) / 256)   // 196

// ======================= warp-MMA helpers (baseline PTX) ====================
__device__ __forceinline__ uint32_t smem_to_u32(const void* p) {
    uint32_t a;
    asm("{ .reg .u64 t; cvta.to.shared.u64 t, %1; cvt.u32.u64 %0, t; }" : "=r"(a) : "l"(p));
    return a;
}
__device__ __forceinline__ void ldsm_x4(uint32_t* r, uint32_t addr) {
    asm volatile("ldmatrix.sync.aligned.m8n8.x4.shared.b16 {%0,%1,%2,%3}, [%4];"
        : "=r"(r[0]), "=r"(r[1]), "=r"(r[2]), "=r"(r[3]) : "r"(addr));
}
__device__ __forceinline__ void ldsm_x2(uint32_t* r, uint32_t addr) {
    asm volatile("ldmatrix.sync.aligned.m8n8.x2.shared.b16 {%0,%1}, [%2];"
        : "=r"(r[0]), "=r"(r[1]) : "r"(addr));
}
__device__ __forceinline__ void mma16816(float* c, const uint32_t* a, const uint32_t* b) {
    asm volatile("mma.sync.aligned.m16n8k16.row.col.f32.bf16.bf16.f32 "
        "{%0,%1,%2,%3}, {%4,%5,%6,%7}, {%8,%9}, {%0,%1,%2,%3};"
        : "+f"(c[0]), "+f"(c[1]), "+f"(c[2]), "+f"(c[3])
        : "r"(a[0]), "r"(a[1]), "r"(a[2]), "r"(a[3]), "r"(b[0]), "r"(b[1]));
}

// ------------------------- scratch (device globals) -------------------------
__device__ __align__(16) int   g_rowptr[NN + 1];
__device__ __align__(16) int   g_blksum[NBLK];
__device__ __align__(16) int   g_cursor[NN];
__device__ __align__(16) int   g_csr[ETOT];
__device__ __align__(16) float g_x0[NN * HIDD];
__device__ __align__(16) float g_agg[NN * 288];     // layer-1 aggregated x0 (4 heads)
__device__ __align__(16) float g_o1[NN * 288];
__device__ __align__(16) float g_h2[NN * HIDD];
__device__ __align__(16) float g_o2[NN * HIDD];
__device__ __align__(16) float g_h3[NN * HIDD];
__device__ __align__(16) float g_o3[NN * HIDD];
__device__ __align__(16) float g_ls1[NN * 4];
__device__ __align__(16) float g_ld1[NN * 4];
__device__ __align__(16) float g_ls2[NN];
__device__ __align__(16) float g_ld2[NN];
__device__ __align__(16) float g_ls3[NN];
__device__ __align__(16) float g_ld3[NN];
__device__ __align__(16) float g_cvec[8 * 72];      // csrc[4][72], cdst[4][72]
// transposed hi/lo weights [N, Kp] (max 288*288)
__device__ __align__(16) __nv_bfloat16 g_wth[288 * 288];
__device__ __align__(16) __nv_bfloat16 g_wtl[288 * 288];

// ------------------------------ CSR build ----------------------------------
__global__ void k_init_deg() {
    int i = blockIdx.x * blockDim.x + threadIdx.x;
    if (i < NN) g_rowptr[i] = 1;
}
__global__ void k_count_deg(const int* __restrict__ ei) {
    int e = blockIdx.x * blockDim.x + threadIdx.x;
    if (e < EE) atomicAdd(&g_rowptr[ei[EE + e]], 1);
}
__global__ void __launch_bounds__(256) k_scan_blk() {
    __shared__ int wsum[8];
    int tid = threadIdx.x, lane = tid & 31, wid = tid >> 5;
    int idx = blockIdx.x * 256 + tid;
    int v = (idx < NN) ? g_rowptr[idx] : 0;
    int x = v;
    #pragma unroll
    for (int o = 1; o < 32; o <<= 1) {
        int y = __shfl_up_sync(0xffffffffu, x, o);
        if (lane >= o) x += y;
    }
    if (lane == 31) wsum[wid] = x;
    __syncthreads();
    if (wid == 0 && lane < 8) {
        int s = wsum[lane];
        #pragma unroll
        for (int o = 1; o < 8; o <<= 1) {
            int y = __shfl_up_sync(0x000000ffu, s, o);
            if (lane >= o) s += y;
        }
        wsum[lane] = s;
    }
    __syncthreads();
    int excl = (wid ? wsum[wid - 1] : 0) + x - v;
    if (idx < NN) g_rowptr[idx] = excl;
    if (tid == 0) g_blksum[blockIdx.x] = wsum[7];
}
__global__ void __launch_bounds__(256) k_scan_top() {
    __shared__ int wsum[8];
    int tid = threadIdx.x, lane = tid & 31, wid = tid >> 5;
    int v = (tid < NBLK) ? g_blksum[tid] : 0;
    int x = v;
    #pragma unroll
    for (int o = 1; o < 32; o <<= 1) {
        int y = __shfl_up_sync(0xffffffffu, x, o);
        if (lane >= o) x += y;
    }
    if (lane == 31) wsum[wid] = x;
    __syncthreads();
    if (wid == 0 && lane < 8) {
        int s = wsum[lane];
        #pragma unroll
        for (int o = 1; o < 8; o <<= 1) {
            int y = __shfl_up_sync(0x000000ffu, s, o);
            if (lane >= o) s += y;
        }
        wsum[lane] = s;
    }
    __syncthreads();
    int excl = (wid ? wsum[wid - 1] : 0) + x - v;
    if (tid < NBLK) g_blksum[tid] = excl;
}
__global__ void k_add_self() {
    int i = blockIdx.x * blockDim.x + threadIdx.x;
    if (i < NN) {
        int r = g_rowptr[i] + g_blksum[i >> 8];
        g_rowptr[i] = r;
        g_csr[r] = i;
        g_cursor[i] = r + 1;
    }
    if (i == 0) g_rowptr[NN] = ETOT;
}
__global__ void k_scatter(const int* __restrict__ ei) {
    int e = blockIdx.x * blockDim.x + threadIdx.x;
    if (e < EE) {
        int s = ei[e];
        int d = ei[EE + e];
        int pos = atomicAdd(&g_cursor[d], 1);
        g_csr[pos] = s;
    }
}

// ----------------- W [K,N] fp32 -> Wt hi/lo [N,Kp] bf16 (tiny) ---------------
__global__ void k_cvtW(const float* __restrict__ W, __nv_bfloat16* __restrict__ H,
                       __nv_bfloat16* __restrict__ L, int K, int N, int Kp)
{
    int idx = blockIdx.x * blockDim.x + threadIdx.x;
    if (idx >= N * Kp) return;
    int n = idx / Kp, k = idx - n * Kp;
    float v = (k < K) ? W[(size_t)k * N + n] : 0.f;
    __nv_bfloat16 h = __float2bfloat16(v);
    H[idx] = h;
    L[idx] = __float2bfloat16(v - __bfloat162float(h));
}

// ---- c vectors for layer-1 logits: csrc_h = W1_h @ a_src_h (72-vector) ------
__global__ void k_cvec(const float* __restrict__ W1,
                       const float* __restrict__ as1, const float* __restrict__ ad1)
{
    int t = blockIdx.x * blockDim.x + threadIdx.x;
    if (t >= 576) return;
    int which = t / 288;            // 0 = src, 1 = dst
    int r = t % 288;
    int h = r / 72, k = r % 72;
    const float* a = (which ? ad1 : as1) + h * 72;
    const float* wrow = W1 + (size_t)k * 288 + h * 72;
    float s = 0.f;
    #pragma unroll 8
    for (int c = 0; c < 72; c++) s += wrow[c] * a[c];
    g_cvec[t] = s;
}

// ---- layer-1 logits straight from x0: ls1[n,h] = x0[n] . csrc_h -------------
__global__ void __launch_bounds__(256) k_logits8(
    const float* __restrict__ x0, float* __restrict__ ls, float* __restrict__ ld)
{
    __shared__ float cs[288], cd[288];
    for (int i = threadIdx.x; i < 288; i += 256) {
        cs[i] = g_cvec[i];
        cd[i] = g_cvec[288 + i];
    }
    __syncthreads();
    int n = blockIdx.x * blockDim.x + threadIdx.x;
    if (n >= NN) return;
    const float* row = x0 + (size_t)n * 72;
    float s[4] = {0.f, 0.f, 0.f, 0.f}, d[4] = {0.f, 0.f, 0.f, 0.f};
    for (int k = 0; k < 72; k += 4) {
        float4 v = *(const float4*)(row + k);
        #pragma unroll
        for (int h = 0; h < 4; h++) {
            float4 a = *(const float4*)(cs + h * 72 + k);
            float4 b = *(const float4*)(cd + h * 72 + k);
            s[h] += v.x * a.x + v.y * a.y + v.z * a.z + v.w * a.w;
            d[h] += v.x * b.x + v.y * b.y + v.z * b.z + v.w * b.w;
        }
    }
    *(float4*)(ls + (size_t)n * 4) = make_float4(s[0], s[1], s[2], s[3]);
    *(float4*)(ld + (size_t)n * 4) = make_float4(d[0], d[1], d[2], d[3]);
}

// -------------------- mma.sync GEMM (generalized) ----------------------------
// C[:, c0:c0+72] = A[:, aColShift? c0 : 0 ...][Kin] @ Wt.T  (Wt rows c0..c0+71)
// A fp32 row stride aStride, split to hi/lo bf16 while staging.
// Optional: fused bias, fused ELU, fused attention logits (layers 2/3).
#define PITCH 40

__global__ void __launch_bounds__(384)
k_mmagemm(const float* __restrict__ A, int aStride, int aColShift,
          const __nv_bfloat16* __restrict__ Bh, const __nv_bfloat16* __restrict__ Bl,
          const float* __restrict__ bias, float* __restrict__ C,
          const float* __restrict__ asrc, const float* __restrict__ adst,
          float* __restrict__ ls, float* __restrict__ ld, int lstride,
          int M, int Kin, int KoutTot, int useBias, int actELU)
{
    __shared__ __nv_bfloat16 sAh[128 * PITCH];
    __shared__ __nv_bfloat16 sAl[128 * PITCH];
    __shared__ __nv_bfloat16 sBh[72 * PITCH];
    __shared__ __nv_bfloat16 sBl[72 * PITCH];
    __shared__ float sLs[128];
    __shared__ float sLd[128];

    int tid = threadIdx.x, wid = tid >> 5, lane = tid & 31;
    int warpM = wid & 3;
    int warpN = wid >> 2;
    int r0 = blockIdx.x * 128;
    int c0 = blockIdx.y * 72;
    int Kp = (Kin + 31) & ~31;
    int aBase = aColShift ? c0 : 0;

    float acc[2][3][4];
    #pragma unroll
    for (int mi = 0; mi < 2; mi++)
        #pragma unroll
        for (int ni = 0; ni < 3; ni++)
            #pragma unroll
            for (int q = 0; q < 4; q++) acc[mi][ni][q] = 0.f;

    uint32_t uAh = smem_to_u32(sAh), uAl = smem_to_u32(sAl);
    uint32_t uBh = smem_to_u32(sBh), uBl = smem_to_u32(sBl);

    int lm = lane >> 3, lj = lane & 7;
    uint32_t aoffA = (uint32_t)(warpM * 32 + (lm & 1) * 8 + lj) * (PITCH * 2) + (lm >> 1) * 16;
    uint32_t aoffB = (uint32_t)(warpN * 24 + lj) * (PITCH * 2) + (lm & 1) * 16;

    for (int kbase = 0; kbase < Kp; kbase += 32) {
        // stage A: 128 rows x 32 cols fp32 -> hi/lo bf16
        #pragma unroll 3
        for (int idx = tid; idx < 1024; idx += 384) {
            int row = idx >> 3, seg = idx & 7;
            int gr = r0 + row;
            int gc = kbase + seg * 4;
            float4 v = make_float4(0.f, 0.f, 0.f, 0.f);
            if (gr < M) {
                const float* ap = A + (size_t)gr * aStride + aBase;
                if (gc + 3 < Kin) v = *(const float4*)(ap + gc);
                else {
                    if (gc + 0 < Kin) v.x = ap[gc + 0];
                    if (gc + 1 < Kin) v.y = ap[gc + 1];
                    if (gc + 2 < Kin) v.z = ap[gc + 2];
                    if (gc + 3 < Kin) v.w = ap[gc + 3];
                }
            }
            __nv_bfloat16 hx = __float2bfloat16(v.x), hy = __float2bfloat16(v.y);
            __nv_bfloat16 hz = __float2bfloat16(v.z), hw = __float2bfloat16(v.w);
            __nv_bfloat162 h01(hx, hy), h23(hz, hw);
            __nv_bfloat162 l01(__float2bfloat16(v.x - __bfloat162float(hx)),
                               __float2bfloat16(v.y - __bfloat162float(hy)));
            __nv_bfloat162 l23(__float2bfloat16(v.z - __bfloat162float(hz)),
                               __float2bfloat16(v.w - __bfloat162float(hw)));
            __nv_bfloat162* ph = (__nv_bfloat162*)(sAh + row * PITCH + seg * 4);
            ph[0] = h01; ph[1] = h23;
            __nv_bfloat162* pl = (__nv_bfloat162*)(sAl + row * PITCH + seg * 4);
            pl[0] = l01; pl[1] = l23;
        }
        // stage B: 72 rows x 32 cols bf16 hi+lo
        for (int idx = tid; idx < 288; idx += 384) {
            int row = idx >> 2, seg = idx & 3;
            *(uint4*)(sBh + row * PITCH + seg * 8) =
                *((const uint4*)(Bh + (size_t)(c0 + row) * Kp + kbase) + seg);
            *(uint4*)(sBl + row * PITCH + seg * 8) =
                *((const uint4*)(Bl + (size_t)(c0 + row) * Kp + kbase) + seg);
        }
        __syncthreads();

        #pragma unroll
        for (int ks = 0; ks < 2; ks++) {
            uint32_t kb = ks * 32;
            uint32_t fah[2][4], fal[2][4], fbh[3][2], fbl[3][2];
            #pragma unroll
            for (int mi = 0; mi < 2; mi++) {
                uint32_t off = aoffA + (uint32_t)mi * 16 * (PITCH * 2) + kb;
                ldsm_x4(fah[mi], uAh + off);
                ldsm_x4(fal[mi], uAl + off);
            }
            #pragma unroll
            for (int ni = 0; ni < 3; ni++) {
                uint32_t off = aoffB + (uint32_t)ni * 8 * (PITCH * 2) + kb;
                ldsm_x2(fbh[ni], uBh + off);
                ldsm_x2(fbl[ni], uBl + off);
            }
            #pragma unroll
            for (int mi = 0; mi < 2; mi++)
                #pragma unroll
                for (int ni = 0; ni < 3; ni++) {
                    mma16816(acc[mi][ni], fah[mi], fbh[ni]);
                    mma16816(acc[mi][ni], fal[mi], fbh[ni]);
                    mma16816(acc[mi][ni], fah[mi], fbl[ni]);
                }
        }
        __syncthreads();
    }

    // ---- store C (+bias, +ELU) ----
    int rb = r0 + warpM * 32 + (lane >> 2);
    int cb = c0 + warpN * 24 + (lane & 3) * 2;
    #pragma unroll
    for (int mi = 0; mi < 2; mi++) {
        #pragma unroll
        for (int ni = 0; ni < 3; ni++) {
            int r = rb + mi * 16;
            int c = cb + ni * 8;
            float2 v0 = make_float2(acc[mi][ni][0], acc[mi][ni][1]);
            float2 v1 = make_float2(acc[mi][ni][2], acc[mi][ni][3]);
            if (useBias) {
                float bx = __ldg(bias + c), by = __ldg(bias + c + 1);
                v0.x += bx; v0.y += by;
                v1.x += bx; v1.y += by;
            }
            if (actELU) {
                v0.x = (v0.x > 0.f) ? v0.x : expm1f(v0.x);
                v0.y = (v0.y > 0.f) ? v0.y : expm1f(v0.y);
                v1.x = (v1.x > 0.f) ? v1.x : expm1f(v1.x);
                v1.y = (v1.y > 0.f) ? v1.y : expm1f(v1.y);
            }
            if (r < M)     *(float2*)(C + (size_t)r * KoutTot + c) = v0;
            if (r + 8 < M) *(float2*)(C + (size_t)(r + 8) * KoutTot + c) = v1;
        }
    }

    // ---- fused attention logits (layers 2/3) ----
    if (ls != nullptr) {
        const float* av = asrc + blockIdx.y * 72;
        const float* dv = adst + blockIdx.y * 72;
        float as6[6], ad6[6];
        #pragma unroll
        for (int t6 = 0; t6 < 6; t6++) {
            int ni = t6 >> 1, j = t6 & 1;
            int cc = warpN * 24 + ni * 8 + (lane & 3) * 2 + j;
            as6[t6] = __ldg(av + cc);
            ad6[t6] = __ldg(dv + cc);
        }
        float sp[4], dp[4];
        #pragma unroll
        for (int mi = 0; mi < 2; mi++)
            #pragma unroll
            for (int half = 0; half < 2; half++) {
                float s = 0.f, d = 0.f;
                #pragma unroll
                for (int ni = 0; ni < 3; ni++) {
                    s += acc[mi][ni][half * 2 + 0] * as6[ni * 2 + 0];
                    s += acc[mi][ni][half * 2 + 1] * as6[ni * 2 + 1];
                    d += acc[mi][ni][half * 2 + 0] * ad6[ni * 2 + 0];
                    d += acc[mi][ni][half * 2 + 1] * ad6[ni * 2 + 1];
                }
                sp[mi * 2 + half] = s;
                dp[mi * 2 + half] = d;
            }
        #pragma unroll
        for (int k = 0; k < 4; k++) {
            #pragma unroll
            for (int o = 1; o < 4; o <<= 1) {
                sp[k] += __shfl_xor_sync(0xffffffffu, sp[k], o);
                dp[k] += __shfl_xor_sync(0xffffffffu, dp[k], o);
            }
        }
        if (tid < 128) { sLs[tid] = 0.f; sLd[tid] = 0.f; }
        __syncthreads();
        if ((lane & 3) == 0) {
            int rloc = warpM * 32 + (lane >> 2);
            atomicAdd(&sLs[rloc],      sp[0]); atomicAdd(&sLd[rloc],      dp[0]);
            atomicAdd(&sLs[rloc + 8],  sp[1]); atomicAdd(&sLd[rloc + 8],  dp[1]);
            atomicAdd(&sLs[rloc + 16], sp[2]); atomicAdd(&sLd[rloc + 16], dp[2]);
            atomicAdd(&sLs[rloc + 24], sp[3]); atomicAdd(&sLd[rloc + 24], dp[3]);
        }
        __syncthreads();
        if (tid < 128) {
            int gr = r0 + tid;
            if (gr < M) {
                ls[(size_t)gr * lstride + blockIdx.y] = sLs[tid];
                ld[(size_t)gr * lstride + blockIdx.y] = sLd[tid];
            }
        }
    }
}

// ------- layer-1 edge pass: aggregate x0 (72 cols) under 4 head alphas -------
__global__ void __launch_bounds__(256) k_edge4agg(
    const float* __restrict__ x0, const float* __restrict__ ls,
    const float* __restrict__ ld, float* __restrict__ agg)
{
    int node = (blockIdx.x * blockDim.x + threadIdx.x) >> 5;
    if (node >= NN) return;
    int lane = threadIdx.x & 31;
    int s0 = g_rowptr[node], s1 = g_rowptr[node + 1];

    float4 ldv = __ldg((const float4*)ld + node);

    float2 a0 = make_float2(0.f, 0.f), a1 = a0, a2 = a0, a3 = a0;
    float  t0 = 0.f, t1 = 0.f, t2 = 0.f, t3 = 0.f;
    float  sum0 = 0.f, sum1 = 0.f, sum2 = 0.f, sum3 = 0.f;
    bool tail = (lane < 8);

    #pragma unroll 2
    for (int i = s0; i < s1; i++) {
        int s = g_csr[i];                        // warp-uniform
        float4 lv = __ldg((const float4*)ls + s);
        float v0 = lv.x + ldv.x; v0 = fmaxf(v0, 0.2f * v0);
        float v1 = lv.y + ldv.y; v1 = fmaxf(v1, 0.2f * v1);
        float v2 = lv.z + ldv.z; v2 = fmaxf(v2, 0.2f * v2);
        float v3 = lv.w + ldv.w; v3 = fmaxf(v3, 0.2f * v3);
        float p0 = __expf(v0), p1 = __expf(v1);
        float p2 = __expf(v2), p3 = __expf(v3);
        sum0 += p0; sum1 += p1; sum2 += p2; sum3 += p3;

        const float* xr = x0 + (size_t)s * 72;
        float2 v = __ldg((const float2*)xr + lane);
        a0.x += p0 * v.x; a0.y += p0 * v.y;
        a1.x += p1 * v.x; a1.y += p1 * v.y;
        a2.x += p2 * v.x; a2.y += p2 * v.y;
        a3.x += p3 * v.x; a3.y += p3 * v.y;
        if (tail) {
            float tv = __ldg(xr + 64 + lane);
            t0 += p0 * tv; t1 += p1 * tv; t2 += p2 * tv; t3 += p3 * tv;
        }
    }

    float i0 = 1.f / fmaxf(sum0, 1e-16f);
    float i1 = 1.f / fmaxf(sum1, 1e-16f);
    float i2 = 1.f / fmaxf(sum2, 1e-16f);
    float i3 = 1.f / fmaxf(sum3, 1e-16f);

    float* o = agg + (size_t)node * 288;
    int c = lane * 2;
    *(float2*)(o + c)       = make_float2(a0.x * i0, a0.y * i0);
    *(float2*)(o + 72 + c)  = make_float2(a1.x * i1, a1.y * i1);
    *(float2*)(o + 144 + c) = make_float2(a2.x * i2, a2.y * i2);
    *(float2*)(o + 216 + c) = make_float2(a3.x * i3, a3.y * i3);
    if (tail) {
        o[64 + lane]  = t0 * i0;
        o[136 + lane] = t1 * i1;
        o[208 + lane] = t2 * i2;
        o[280 + lane] = t3 * i3;
    }
}

// --------------- single-head edge pass (layers 2/3, unchanged) ---------------
__global__ void __launch_bounds__(256) k_edge1(
    const float* __restrict__ hfeat, const float* __restrict__ ls,
    const float* __restrict__ ld, const float* __restrict__ bias,
    float* __restrict__ outp)
{
    int node = (blockIdx.x * blockDim.x + threadIdx.x) >> 5;
    if (node >= NN) return;
    int lane = threadIdx.x & 31;
    int s0 = g_rowptr[node], s1 = g_rowptr[node + 1];

    float ldv = __ldg(ld + node);
    float2 acc = make_float2(0.f, 0.f);
    float  acc2 = 0.f;
    float  sum = 0.f;
    bool tail = (lane < 8);

    #pragma unroll 4
    for (int i = s0; i < s1; i++) {
        int s = g_csr[i];
        float v = __ldg(ls + s) + ldv;
        v = fmaxf(v, 0.2f * v);
        float p = __expf(v);
        sum += p;
        const float* hr = hfeat + (size_t)s * 72;
        float2 hA = __ldg((const float2*)hr + lane);
        acc.x += p * hA.x;
        acc.y += p * hA.y;
        if (tail) acc2 += p * __ldg(hr + 64 + lane);
    }

    float inv = 1.f / fmaxf(sum, 1e-16f);
    float* o = outp + (size_t)node * 72;
    {
        int c = lane * 2;
        float bx = __ldg(bias + c), by = __ldg(bias + c + 1);
        float2 r;
        r.x = acc.x * inv + bx; r.x = (r.x > 0.f) ? r.x : expm1f(r.x);
        r.y = acc.y * inv + by; r.y = (r.y > 0.f) ? r.y : expm1f(r.y);
        *(float2*)(o + c) = r;
    }
    if (tail) {
        int c = 64 + lane;
        float v = acc2 * inv + __ldg(bias + c);
        o[c] = (v > 0.f) ? v : expm1f(v);
    }
}

// ----------------------- final residual + score MLP -------------------------
__global__ void __launch_bounds__(256) k_final(
    const float* __restrict__ h3, const float* __restrict__ x0,
    const float* __restrict__ Ws1, const float* __restrict__ bs1,
    const float* __restrict__ Ws2, const float* __restrict__ bs2,
    float* __restrict__ out)
{
    __shared__ float w1s[72 * 32];
    __shared__ float w2s[32];
    __shared__ float b1s[32];
    __shared__ float b2s;
    for (int i = threadIdx.x; i < 72 * 32; i += blockDim.x) w1s[i] = Ws1[i];
    if (threadIdx.x < 32) {
        w2s[threadIdx.x] = Ws2[threadIdx.x];
        b1s[threadIdx.x] = bs1[threadIdx.x];
    }
    if (threadIdx.x == 0) b2s = bs2[0];
    __syncthreads();

    int n = blockIdx.x * blockDim.x + threadIdx.x;
    if (n >= NN) return;
    float t[32];
    #pragma unroll
    for (int j = 0; j < 32; j++) t[j] = b1s[j];
    const float* hr = h3 + (size_t)n * 72;
    const float* xr = x0 + (size_t)n * 72;
    for (int k = 0; k < 72; k++) {
        float v = __ldg(hr + k) + __ldg(xr + k);
        #pragma unroll
        for (int j = 0; j < 32; j += 4) {
            float4 w = *(const float4*)&w1s[k * 32 + j];
            t[j + 0] += v * w.x;
            t[j + 1] += v * w.y;
            t[j + 2] += v * w.z;
            t[j + 3] += v * w.w;
        }
    }
    float s = b2s;
    #pragma unroll
    for (int j = 0; j < 32; j++) s += fmaxf(t[j], 0.f) * w2s[j];
    out[n] = s;
}

// ------------------------------ launch ---------------------------------------
extern "C" void kernel_launch(void* const* d_in, const int* in_sizes, int n_in,
                              void* d_out, int out_size)
{
    const float* x    = (const float*)d_in[0];
    const int*   ei   = (const int*)d_in[1];
    const float* W_in = (const float*)d_in[2];
    const float* b_in = (const float*)d_in[3];
    const float* W1   = (const float*)d_in[4];
    const float* as1  = (const float*)d_in[5];
    const float* ad1  = (const float*)d_in[6];
    const float* b1   = (const float*)d_in[7];
    const float* W2   = (const float*)d_in[8];
    const float* as2  = (const float*)d_in[9];
    const float* ad2  = (const float*)d_in[10];
    const float* b2   = (const float*)d_in[11];
    const float* W3   = (const float*)d_in[12];
    const float* as3  = (const float*)d_in[13];
    const float* ad3  = (const float*)d_in[14];
    const float* b3   = (const float*)d_in[15];
    const float* Ws1  = (const float*)d_in[16];
    const float* bs1  = (const float*)d_in[17];
    const float* Ws2  = (const float*)d_in[18];
    const float* bs2  = (const float*)d_in[19];
    float* out = (float*)d_out;

    float *px0, *pagg, *po1, *ph2, *po2, *ph3, *po3;
    float *pls1, *pld1, *pls2, *pld2, *pls3, *pld3;
    __nv_bfloat16 *pwth, *pwtl;
    cudaGetSymbolAddress((void**)&px0,  g_x0);
    cudaGetSymbolAddress((void**)&pagg, g_agg);
    cudaGetSymbolAddress((void**)&po1,  g_o1);
    cudaGetSymbolAddress((void**)&ph2,  g_h2);
    cudaGetSymbolAddress((void**)&po2,  g_o2);
    cudaGetSymbolAddress((void**)&ph3,  g_h3);
    cudaGetSymbolAddress((void**)&po3,  g_o3);
    cudaGetSymbolAddress((void**)&pls1, g_ls1);
    cudaGetSymbolAddress((void**)&pld1, g_ld1);
    cudaGetSymbolAddress((void**)&pls2, g_ls2);
    cudaGetSymbolAddress((void**)&pld2, g_ld2);
    cudaGetSymbolAddress((void**)&pls3, g_ls3);
    cudaGetSymbolAddress((void**)&pld3, g_ld3);
    cudaGetSymbolAddress((void**)&pwth, g_wth);
    cudaGetSymbolAddress((void**)&pwtl, g_wtl);

    // --- layer 0 + CSR begin (profiled capture slot 3 = gemm0) ---
    k_cvtW<<<(72 * 256 + 255) / 256, 256>>>(W_in, pwth, pwtl, 256, 72, 256);  // 0
    k_init_deg<<<(NN + 255) / 256, 256>>>();                                  // 1
    k_count_deg<<<(EE + 255) / 256, 256>>>(ei);                               // 2
    k_mmagemm<<<dim3(391, 1), 384>>>(x, 256, 0, pwth, pwtl, b_in, px0,
                                     nullptr, nullptr, nullptr, nullptr, 1,
                                     NN, 256, 72, 1, 0);                      // 3 (profiled)
    k_scan_blk<<<NBLK, 256>>>();
    k_scan_top<<<1, 256>>>();
    k_add_self<<<(NN + 255) / 256, 256>>>();
    k_scatter<<<(EE + 255) / 256, 256>>>(ei);

    // --- layer 1: logits from x0 via c-vectors; aggregate x0; per-head GEMM ---
    k_cvec<<<3, 256>>>(W1, as1, ad1);
    k_logits8<<<(NN + 255) / 256, 256>>>(px0, pls1, pld1);
    k_edge4agg<<<(NN * 32) / 256, 256>>>(px0, pls1, pld1, pagg);
    k_cvtW<<<(288 * 96 + 255) / 256, 256>>>(W1, pwth, pwtl, 72, 288, 96);
    // o1[:, h*72:(h+1)*72] = ELU(agg[:, h, :] @ W1_h + b1)
    k_mmagemm<<<dim3(391, 4), 384>>>(pagg, 288, 1, pwth, pwtl, b1, po1,
                                     nullptr, nullptr, nullptr, nullptr, 1,
                                     NN, 72, 288, 1, 1);

    // --- layer 2 (1 head) ---
    k_cvtW<<<(72 * 288 + 255) / 256, 256>>>(W2, pwth, pwtl, 288, 72, 288);
    k_mmagemm<<<dim3(391, 1), 384>>>(po1, 288, 0, pwth, pwtl, nullptr, ph2,
                                     as2, ad2, pls2, pld2, 1,
                                     NN, 288, 72, 0, 0);
    k_edge1<<<(NN * 32) / 256, 256>>>(ph2, pls2, pld2, b2, po2);

    // --- layer 3 (1 head) ---
    k_cvtW<<<(72 * 96 + 255) / 256, 256>>>(W3, pwth, pwtl, 72, 72, 96);
    k_mmagemm<<<dim3(391, 1), 384>>>(po2, 72, 0, pwth, pwtl, nullptr, ph3,
                                     as3, ad3, pls3, pld3, 1,
                                     NN, 72, 72, 0, 0);
    k_edge1<<<(NN * 32) / 256, 256>>>(ph3, pls3, pld3, b3, po3);

    // --- residual + score MLP ---
    k_final<<<(NN + 255) / 256, 256>>>(po3, px0, Ws1, bs1, Ws2, bs2, out);
}

// round 7
// speedup vs baseline: 1.6389x; 1.1734x over previous
#include <cuda_runtime.h>
#include <cuda_bf16.h>
#include <math.h>
#include <stdint.h>

#define NN   50000
#define EE   800000
#define ETOT (NN + EE)
#define IND  256
#define HIDD 72
#define NBLK ((NN + 255) / 256)   // 196

// ======================= warp-MMA helpers (baseline PTX) ====================
__device__ __forceinline__ uint32_t smem_to_u32(const void* p) {
    uint32_t a;
    asm("{ .reg .u64 t; cvta.to.shared.u64 t, %1; cvt.u32.u64 %0, t; }" : "=r"(a) : "l"(p));
    return a;
}
__device__ __forceinline__ void ldsm_x4(uint32_t* r, uint32_t addr) {
    asm volatile("ldmatrix.sync.aligned.m8n8.x4.shared.b16 {%0,%1,%2,%3}, [%4];"
        : "=r"(r[0]), "=r"(r[1]), "=r"(r[2]), "=r"(r[3]) : "r"(addr));
}
__device__ __forceinline__ void ldsm_x2(uint32_t* r, uint32_t addr) {
    asm volatile("ldmatrix.sync.aligned.m8n8.x2.shared.b16 {%0,%1}, [%2];"
        : "=r"(r[0]), "=r"(r[1]) : "r"(addr));
}
__device__ __forceinline__ void mma16816(float* c, const uint32_t* a, const uint32_t* b) {
    asm volatile("mma.sync.aligned.m16n8k16.row.col.f32.bf16.bf16.f32 "
        "{%0,%1,%2,%3}, {%4,%5,%6,%7}, {%8,%9}, {%0,%1,%2,%3};"
        : "+f"(c[0]), "+f"(c[1]), "+f"(c[2]), "+f"(c[3])
        : "r"(a[0]), "r"(a[1]), "r"(a[2]), "r"(a[3]), "r"(b[0]), "r"(b[1]));
}
__device__ __forceinline__ void cp16(uint32_t s, const void* g) {
    asm volatile("cp.async.cg.shared.global [%0], [%1], 16;" :: "r"(s), "l"(g));
}
#define CP_COMMIT() asm volatile("cp.async.commit_group;" ::: "memory")
#define CP_WAIT(n)  asm volatile("cp.async.wait_group %0;" :: "n"(n) : "memory")

// ------------------------- scratch (device globals) -------------------------
__device__ __align__(16) int   g_rowptr[NN + 1];
__device__ __align__(16) int   g_blksum[NBLK];
__device__ __align__(16) int   g_cursor[NN];
__device__ __align__(16) int   g_csr[ETOT];
__device__ __align__(16) float g_x0[NN * HIDD];
__device__ __align__(16) float g_agg[NN * 288];
__device__ __align__(16) float g_o1[NN * 288];
__device__ __align__(16) float g_h2[NN * HIDD];
__device__ __align__(16) float g_o2[NN * HIDD];
__device__ __align__(16) float g_h3[NN * HIDD];
__device__ __align__(16) float g_o3[NN * HIDD];
__device__ __align__(16) float g_ls1[NN * 4];
__device__ __align__(16) float g_ld1[NN * 4];
__device__ __align__(16) float g_ls2[NN];
__device__ __align__(16) float g_ld2[NN];
__device__ __align__(16) float g_ls3[NN];
__device__ __align__(16) float g_ld3[NN];
__device__ __align__(16) float g_cvec[8 * 72];
__device__ __align__(16) __nv_bfloat16 g_wth[288 * 288];
__device__ __align__(16) __nv_bfloat16 g_wtl[288 * 288];

// ------------------------------ CSR build ----------------------------------
__global__ void k_init_deg() {
    int i = blockIdx.x * blockDim.x + threadIdx.x;
    if (i < NN) g_rowptr[i] = 1;
}
__global__ void k_count_deg(const int* __restrict__ ei) {
    int e = blockIdx.x * blockDim.x + threadIdx.x;
    if (e < EE) atomicAdd(&g_rowptr[ei[EE + e]], 1);
}
__global__ void __launch_bounds__(256) k_scan_blk() {
    __shared__ int wsum[8];
    int tid = threadIdx.x, lane = tid & 31, wid = tid >> 5;
    int idx = blockIdx.x * 256 + tid;
    int v = (idx < NN) ? g_rowptr[idx] : 0;
    int x = v;
    #pragma unroll
    for (int o = 1; o < 32; o <<= 1) {
        int y = __shfl_up_sync(0xffffffffu, x, o);
        if (lane >= o) x += y;
    }
    if (lane == 31) wsum[wid] = x;
    __syncthreads();
    if (wid == 0 && lane < 8) {
        int s = wsum[lane];
        #pragma unroll
        for (int o = 1; o < 8; o <<= 1) {
            int y = __shfl_up_sync(0x000000ffu, s, o);
            if (lane >= o) s += y;
        }
        wsum[lane] = s;
    }
    __syncthreads();
    int excl = (wid ? wsum[wid - 1] : 0) + x - v;
    if (idx < NN) g_rowptr[idx] = excl;
    if (tid == 0) g_blksum[blockIdx.x] = wsum[7];
}
__global__ void __launch_bounds__(256) k_scan_top() {
    __shared__ int wsum[8];
    int tid = threadIdx.x, lane = tid & 31, wid = tid >> 5;
    int v = (tid < NBLK) ? g_blksum[tid] : 0;
    int x = v;
    #pragma unroll
    for (int o = 1; o < 32; o <<= 1) {
        int y = __shfl_up_sync(0xffffffffu, x, o);
        if (lane >= o) x += y;
    }
    if (lane == 31) wsum[wid] = x;
    __syncthreads();
    if (wid == 0 && lane < 8) {
        int s = wsum[lane];
        #pragma unroll
        for (int o = 1; o < 8; o <<= 1) {
            int y = __shfl_up_sync(0x000000ffu, s, o);
            if (lane >= o) s += y;
        }
        wsum[lane] = s;
    }
    __syncthreads();
    int excl = (wid ? wsum[wid - 1] : 0) + x - v;
    if (tid < NBLK) g_blksum[tid] = excl;
}
__global__ void k_add_self() {
    int i = blockIdx.x * blockDim.x + threadIdx.x;
    if (i < NN) {
        int r = g_rowptr[i] + g_blksum[i >> 8];
        g_rowptr[i] = r;
        g_csr[r] = i;
        g_cursor[i] = r + 1;
    }
    if (i == 0) g_rowptr[NN] = ETOT;
}
__global__ void k_scatter(const int* __restrict__ ei) {
    int e = blockIdx.x * blockDim.x + threadIdx.x;
    if (e < EE) {
        int s = ei[e];
        int d = ei[EE + e];
        int pos = atomicAdd(&g_cursor[d], 1);
        g_csr[pos] = s;
    }
}

// ----------------- W [K,N] fp32 -> Wt hi/lo [N,Kp] bf16 (tiny) ---------------
__global__ void k_cvtW(const float* __restrict__ W, __nv_bfloat16* __restrict__ H,
                       __nv_bfloat16* __restrict__ L, int K, int N, int Kp)
{
    int idx = blockIdx.x * blockDim.x + threadIdx.x;
    if (idx >= N * Kp) return;
    int n = idx / Kp, k = idx - n * Kp;
    float v = (k < K) ? W[(size_t)k * N + n] : 0.f;
    __nv_bfloat16 h = __float2bfloat16(v);
    H[idx] = h;
    L[idx] = __float2bfloat16(v - __bfloat162float(h));
}

// ---- c vectors for layer-1 logits: csrc_h = W1_h @ a_src_h (72-vector) ------
__global__ void k_cvec(const float* __restrict__ W1,
                       const float* __restrict__ as1, const float* __restrict__ ad1)
{
    int t = blockIdx.x * blockDim.x + threadIdx.x;
    if (t >= 576) return;
    int which = t / 288;
    int r = t % 288;
    int h = r / 72, k = r % 72;
    const float* a = (which ? ad1 : as1) + h * 72;
    const float* wrow = W1 + (size_t)k * 288 + h * 72;
    float s = 0.f;
    #pragma unroll 8
    for (int c = 0; c < 72; c++) s += wrow[c] * a[c];
    g_cvec[t] = s;
}

// ---- layer-1 logits straight from x0 ----------------------------------------
__global__ void __launch_bounds__(256) k_logits8(
    const float* __restrict__ x0, float* __restrict__ ls, float* __restrict__ ld)
{
    __shared__ float cs[288], cd[288];
    for (int i = threadIdx.x; i < 288; i += 256) {
        cs[i] = g_cvec[i];
        cd[i] = g_cvec[288 + i];
    }
    __syncthreads();
    int n = blockIdx.x * blockDim.x + threadIdx.x;
    if (n >= NN) return;
    const float* row = x0 + (size_t)n * 72;
    float s[4] = {0.f, 0.f, 0.f, 0.f}, d[4] = {0.f, 0.f, 0.f, 0.f};
    for (int k = 0; k < 72; k += 4) {
        float4 v = *(const float4*)(row + k);
        #pragma unroll
        for (int h = 0; h < 4; h++) {
            float4 a = *(const float4*)(cs + h * 72 + k);
            float4 b = *(const float4*)(cd + h * 72 + k);
            s[h] += v.x * a.x + v.y * a.y + v.z * a.z + v.w * a.w;
            d[h] += v.x * b.x + v.y * b.y + v.z * b.z + v.w * b.w;
        }
    }
    *(float4*)(ls + (size_t)n * 4) = make_float4(s[0], s[1], s[2], s[3]);
    *(float4*)(ld + (size_t)n * 4) = make_float4(d[0], d[1], d[2], d[3]);
}

// -------------------- pipelined mma.sync GEMM --------------------------------
// A fp32 (stride aStride, col base aColShift*c0) staged via register pipeline
// with in-flight hi/lo bf16 split; B (pre-split bf16) via cp.async double buffer.
#define PITCH 40
#define BPART (72 * PITCH * 2)   // bytes per B part

__global__ void __launch_bounds__(384, 2)
k_mmagemm(const float* __restrict__ A, int aStride, int aColShift,
          const __nv_bfloat16* __restrict__ Bh, const __nv_bfloat16* __restrict__ Bl,
          const float* __restrict__ bias, float* __restrict__ C,
          const float* __restrict__ asrc, const float* __restrict__ adst,
          float* __restrict__ ls, float* __restrict__ ld, int lstride,
          int M, int Kin, int KoutTot, int useBias, int actELU)
{
    __shared__ __nv_bfloat16 sAh[128 * PITCH];
    __shared__ __nv_bfloat16 sAl[128 * PITCH];
    __shared__ __nv_bfloat16 sB[2][2][72 * PITCH];   // [buf][hi/lo]
    __shared__ float sLs[128];
    __shared__ float sLd[128];

    int tid = threadIdx.x, wid = tid >> 5, lane = tid & 31;
    int warpM = wid & 3;
    int warpN = wid >> 2;
    int r0 = blockIdx.x * 128;
    int c0 = blockIdx.y * 72;
    int Kp = (Kin + 31) & ~31;
    int aBase = aColShift ? c0 : 0;
    const int chunks = Kp >> 5;

    float acc[2][3][4];
    #pragma unroll
    for (int mi = 0; mi < 2; mi++)
        #pragma unroll
        for (int ni = 0; ni < 3; ni++)
            #pragma unroll
            for (int q = 0; q < 4; q++) acc[mi][ni][q] = 0.f;

    uint32_t uAh = smem_to_u32(sAh), uAl = smem_to_u32(sAl);
    uint32_t uB  = smem_to_u32(sB);

    int lm = lane >> 3, lj = lane & 7;
    uint32_t aoffA = (uint32_t)(warpM * 32 + (lm & 1) * 8 + lj) * (PITCH * 2) + (lm >> 1) * 16;
    uint32_t aoffB = (uint32_t)(warpN * 24 + lj) * (PITCH * 2) + (lm & 1) * 16;

    // ---- pipeline helpers ----
    auto loadA4 = [&](int idx, int kbase) -> float4 {
        int row = idx >> 3, seg = idx & 7;
        int gr = r0 + row;
        int gc = kbase + seg * 4;
        float4 v = make_float4(0.f, 0.f, 0.f, 0.f);
        if (gr < M) {
            const float* ap = A + (size_t)gr * aStride + aBase;
            if (gc + 3 < Kin) v = *(const float4*)(ap + gc);
            else {
                if (gc + 0 < Kin) v.x = ap[gc + 0];
                if (gc + 1 < Kin) v.y = ap[gc + 1];
                if (gc + 2 < Kin) v.z = ap[gc + 2];
                if (gc + 3 < Kin) v.w = ap[gc + 3];
            }
        }
        return v;
    };
    auto storeA4 = [&](int idx, float4 v) {
        int row = idx >> 3, seg = idx & 7;
        __nv_bfloat16 hx = __float2bfloat16(v.x), hy = __float2bfloat16(v.y);
        __nv_bfloat16 hz = __float2bfloat16(v.z), hw = __float2bfloat16(v.w);
        __nv_bfloat162* ph = (__nv_bfloat162*)(sAh + row * PITCH + seg * 4);
        ph[0] = __nv_bfloat162(hx, hy);
        ph[1] = __nv_bfloat162(hz, hw);
        __nv_bfloat162* pl = (__nv_bfloat162*)(sAl + row * PITCH + seg * 4);
        pl[0] = __nv_bfloat162(__float2bfloat16(v.x - __bfloat162float(hx)),
                               __float2bfloat16(v.y - __bfloat162float(hy)));
        pl[1] = __nv_bfloat162(__float2bfloat16(v.z - __bfloat162float(hz)),
                               __float2bfloat16(v.w - __bfloat162float(hw)));
    };
    auto stageB = [&](int ch) {
        int kbase = ch << 5;
        int buf = ch & 1;
        #pragma unroll
        for (int rep = 0; rep < 2; rep++) {
            int idx = tid + rep * 384;
            if (idx < 576) {
                int part = (idx >= 288);
                int e = part ? idx - 288 : idx;
                int r = e >> 2, seg = e & 3;
                const __nv_bfloat16* gp =
                    (part ? Bl : Bh) + (size_t)(c0 + r) * Kp + kbase + seg * 8;
                uint32_t sp = uB + (uint32_t)(buf * 2 + part) * BPART
                                 + (uint32_t)r * (PITCH * 2) + seg * 16;
                cp16(sp, gp);
            }
        }
    };

    // ---- prologue ----
    stageB(0);
    CP_COMMIT();
    float4 aReg0 = loadA4(tid, 0);
    float4 aReg1 = loadA4(tid + 384, 0);
    float4 aReg2 = (tid < 256) ? loadA4(tid + 768, 0) : make_float4(0.f, 0.f, 0.f, 0.f);

    for (int ch = 0; ch < chunks; ch++) {
        // commit staged A registers to smem (with hi/lo split)
        storeA4(tid, aReg0);
        storeA4(tid + 384, aReg1);
        if (tid < 256) storeA4(tid + 768, aReg2);

        bool more = (ch + 1 < chunks);
        if (more) {
            int kb = (ch + 1) << 5;
            aReg0 = loadA4(tid, kb);
            aReg1 = loadA4(tid + 384, kb);
            if (tid < 256) aReg2 = loadA4(tid + 768, kb);
            stageB(ch + 1);
            CP_COMMIT();
            CP_WAIT(1);
        } else {
            CP_WAIT(0);
        }
        __syncthreads();

        uint32_t bufOff = (uint32_t)(ch & 1) * 2 * BPART;
        #pragma unroll
        for (int ks = 0; ks < 2; ks++) {
            uint32_t kb = ks * 32;
            uint32_t fah[2][4], fal[2][4], fbh[3][2], fbl[3][2];
            #pragma unroll
            for (int mi = 0; mi < 2; mi++) {
                uint32_t off = aoffA + (uint32_t)mi * 16 * (PITCH * 2) + kb;
                ldsm_x4(fah[mi], uAh + off);
                ldsm_x4(fal[mi], uAl + off);
            }
            #pragma unroll
            for (int ni = 0; ni < 3; ni++) {
                uint32_t off = aoffB + (uint32_t)ni * 8 * (PITCH * 2) + kb;
                ldsm_x2(fbh[ni], uB + bufOff + off);
                ldsm_x2(fbl[ni], uB + bufOff + BPART + off);
            }
            #pragma unroll
            for (int mi = 0; mi < 2; mi++)
                #pragma unroll
                for (int ni = 0; ni < 3; ni++) {
                    mma16816(acc[mi][ni], fah[mi], fbh[ni]);
                    mma16816(acc[mi][ni], fal[mi], fbh[ni]);
                    mma16816(acc[mi][ni], fah[mi], fbl[ni]);
                }
        }
        __syncthreads();
    }

    // ---- store C (+bias, +ELU) ----
    int rb = r0 + warpM * 32 + (lane >> 2);
    int cb = c0 + warpN * 24 + (lane & 3) * 2;
    #pragma unroll
    for (int mi = 0; mi < 2; mi++) {
        #pragma unroll
        for (int ni = 0; ni < 3; ni++) {
            int r = rb + mi * 16;
            int c = cb + ni * 8;
            float2 v0 = make_float2(acc[mi][ni][0], acc[mi][ni][1]);
            float2 v1 = make_float2(acc[mi][ni][2], acc[mi][ni][3]);
            if (useBias) {
                float bx = __ldg(bias + c), by = __ldg(bias + c + 1);
                v0.x += bx; v0.y += by;
                v1.x += bx; v1.y += by;
            }
            if (actELU) {
                v0.x = (v0.x > 0.f) ? v0.x : expm1f(v0.x);
                v0.y = (v0.y > 0.f) ? v0.y : expm1f(v0.y);
                v1.x = (v1.x > 0.f) ? v1.x : expm1f(v1.x);
                v1.y = (v1.y > 0.f) ? v1.y : expm1f(v1.y);
            }
            if (r < M)     *(float2*)(C + (size_t)r * KoutTot + c) = v0;
            if (r + 8 < M) *(float2*)(C + (size_t)(r + 8) * KoutTot + c) = v1;
        }
    }

    // ---- fused attention logits (layers 2/3) ----
    if (ls != nullptr) {
        const float* av = asrc + blockIdx.y * 72;
        const float* dv = adst + blockIdx.y * 72;
        float as6[6], ad6[6];
        #pragma unroll
        for (int t6 = 0; t6 < 6; t6++) {
            int ni = t6 >> 1, j = t6 & 1;
            int cc = warpN * 24 + ni * 8 + (lane & 3) * 2 + j;
            as6[t6] = __ldg(av + cc);
            ad6[t6] = __ldg(dv + cc);
        }
        float sp[4], dp[4];
        #pragma unroll
        for (int mi = 0; mi < 2; mi++)
            #pragma unroll
            for (int half = 0; half < 2; half++) {
                float s = 0.f, d = 0.f;
                #pragma unroll
                for (int ni = 0; ni < 3; ni++) {
                    s += acc[mi][ni][half * 2 + 0] * as6[ni * 2 + 0];
                    s += acc[mi][ni][half * 2 + 1] * as6[ni * 2 + 1];
                    d += acc[mi][ni][half * 2 + 0] * ad6[ni * 2 + 0];
                    d += acc[mi][ni][half * 2 + 1] * ad6[ni * 2 + 1];
                }
                sp[mi * 2 + half] = s;
                dp[mi * 2 + half] = d;
            }
        #pragma unroll
        for (int k = 0; k < 4; k++) {
            #pragma unroll
            for (int o = 1; o < 4; o <<= 1) {
                sp[k] += __shfl_xor_sync(0xffffffffu, sp[k], o);
                dp[k] += __shfl_xor_sync(0xffffffffu, dp[k], o);
            }
        }
        if (tid < 128) { sLs[tid] = 0.f; sLd[tid] = 0.f; }
        __syncthreads();
        if ((lane & 3) == 0) {
            int rloc = warpM * 32 + (lane >> 2);
            atomicAdd(&sLs[rloc],      sp[0]); atomicAdd(&sLd[rloc],      dp[0]);
            atomicAdd(&sLs[rloc + 8],  sp[1]); atomicAdd(&sLd[rloc + 8],  dp[1]);
            atomicAdd(&sLs[rloc + 16], sp[2]); atomicAdd(&sLd[rloc + 16], dp[2]);
            atomicAdd(&sLs[rloc + 24], sp[3]); atomicAdd(&sLd[rloc + 24], dp[3]);
        }
        __syncthreads();
        if (tid < 128) {
            int gr = r0 + tid;
            if (gr < M) {
                ls[(size_t)gr * lstride + blockIdx.y] = sLs[tid];
                ld[(size_t)gr * lstride + blockIdx.y] = sLd[tid];
            }
        }
    }
}

// ------- layer-1 edge pass: aggregate x0 (72 cols) under 4 head alphas -------
__global__ void __launch_bounds__(256) k_edge4agg(
    const float* __restrict__ x0, const float* __restrict__ ls,
    const float* __restrict__ ld, float* __restrict__ agg)
{
    int node = (blockIdx.x * blockDim.x + threadIdx.x) >> 5;
    if (node >= NN) return;
    int lane = threadIdx.x & 31;
    int s0 = g_rowptr[node], s1 = g_rowptr[node + 1];

    float4 ldv = __ldg((const float4*)ld + node);

    float2 a0 = make_float2(0.f, 0.f), a1 = a0, a2 = a0, a3 = a0;
    float  t0 = 0.f, t1 = 0.f, t2 = 0.f, t3 = 0.f;
    float  sum0 = 0.f, sum1 = 0.f, sum2 = 0.f, sum3 = 0.f;
    bool tail = (lane < 8);

    #pragma unroll 2
    for (int i = s0; i < s1; i++) {
        int s = g_csr[i];
        float4 lv = __ldg((const float4*)ls + s);
        float v0 = lv.x + ldv.x; v0 = fmaxf(v0, 0.2f * v0);
        float v1 = lv.y + ldv.y; v1 = fmaxf(v1, 0.2f * v1);
        float v2 = lv.z + ldv.z; v2 = fmaxf(v2, 0.2f * v2);
        float v3 = lv.w + ldv.w; v3 = fmaxf(v3, 0.2f * v3);
        float p0 = __expf(v0), p1 = __expf(v1);
        float p2 = __expf(v2), p3 = __expf(v3);
        sum0 += p0; sum1 += p1; sum2 += p2; sum3 += p3;

        const float* xr = x0 + (size_t)s * 72;
        float2 v = __ldg((const float2*)xr + lane);
        a0.x += p0 * v.x; a0.y += p0 * v.y;
        a1.x += p1 * v.x; a1.y += p1 * v.y;
        a2.x += p2 * v.x; a2.y += p2 * v.y;
        a3.x += p3 * v.x; a3.y += p3 * v.y;
        if (tail) {
            float tv = __ldg(xr + 64 + lane);
            t0 += p0 * tv; t1 += p1 * tv; t2 += p2 * tv; t3 += p3 * tv;
        }
    }

    float i0 = 1.f / fmaxf(sum0, 1e-16f);
    float i1 = 1.f / fmaxf(sum1, 1e-16f);
    float i2 = 1.f / fmaxf(sum2, 1e-16f);
    float i3 = 1.f / fmaxf(sum3, 1e-16f);

    float* o = agg + (size_t)node * 288;
    int c = lane * 2;
    *(float2*)(o + c)       = make_float2(a0.x * i0, a0.y * i0);
    *(float2*)(o + 72 + c)  = make_float2(a1.x * i1, a1.y * i1);
    *(float2*)(o + 144 + c) = make_float2(a2.x * i2, a2.y * i2);
    *(float2*)(o + 216 + c) = make_float2(a3.x * i3, a3.y * i3);
    if (tail) {
        o[64 + lane]  = t0 * i0;
        o[136 + lane] = t1 * i1;
        o[208 + lane] = t2 * i2;
        o[280 + lane] = t3 * i3;
    }
}

// --------------- single-head edge pass (layers 2/3) --------------------------
__global__ void __launch_bounds__(256) k_edge1(
    const float* __restrict__ hfeat, const float* __restrict__ ls,
    const float* __restrict__ ld, const float* __restrict__ bias,
    float* __restrict__ outp)
{
    int node = (blockIdx.x * blockDim.x + threadIdx.x) >> 5;
    if (node >= NN) return;
    int lane = threadIdx.x & 31;
    int s0 = g_rowptr[node], s1 = g_rowptr[node + 1];

    float ldv = __ldg(ld + node);
    float2 acc = make_float2(0.f, 0.f);
    float  acc2 = 0.f;
    float  sum = 0.f;
    bool tail = (lane < 8);

    #pragma unroll 4
    for (int i = s0; i < s1; i++) {
        int s = g_csr[i];
        float v = __ldg(ls + s) + ldv;
        v = fmaxf(v, 0.2f * v);
        float p = __expf(v);
        sum += p;
        const float* hr = hfeat + (size_t)s * 72;
        float2 hA = __ldg((const float2*)hr + lane);
        acc.x += p * hA.x;
        acc.y += p * hA.y;
        if (tail) acc2 += p * __ldg(hr + 64 + lane);
    }

    float inv = 1.f / fmaxf(sum, 1e-16f);
    float* o = outp + (size_t)node * 72;
    {
        int c = lane * 2;
        float bx = __ldg(bias + c), by = __ldg(bias + c + 1);
        float2 r;
        r.x = acc.x * inv + bx; r.x = (r.x > 0.f) ? r.x : expm1f(r.x);
        r.y = acc.y * inv + by; r.y = (r.y > 0.f) ? r.y : expm1f(r.y);
        *(float2*)(o + c) = r;
    }
    if (tail) {
        int c = 64 + lane;
        float v = acc2 * inv + __ldg(bias + c);
        o[c] = (v > 0.f) ? v : expm1f(v);
    }
}

// ----------------------- final residual + score MLP -------------------------
__global__ void __launch_bounds__(256) k_final(
    const float* __restrict__ h3, const float* __restrict__ x0,
    const float* __restrict__ Ws1, const float* __restrict__ bs1,
    const float* __restrict__ Ws2, const float* __restrict__ bs2,
    float* __restrict__ out)
{
    __shared__ float w1s[72 * 32];
    __shared__ float w2s[32];
    __shared__ float b1s[32];
    __shared__ float b2s;
    for (int i = threadIdx.x; i < 72 * 32; i += blockDim.x) w1s[i] = Ws1[i];
    if (threadIdx.x < 32) {
        w2s[threadIdx.x] = Ws2[threadIdx.x];
        b1s[threadIdx.x] = bs1[threadIdx.x];
    }
    if (threadIdx.x == 0) b2s = bs2[0];
    __syncthreads();

    int n = blockIdx.x * blockDim.x + threadIdx.x;
    if (n >= NN) return;
    float t[32];
    #pragma unroll
    for (int j = 0; j < 32; j++) t[j] = b1s[j];
    const float* hr = h3 + (size_t)n * 72;
    const float* xr = x0 + (size_t)n * 72;
    for (int k = 0; k < 72; k++) {
        float v = __ldg(hr + k) + __ldg(xr + k);
        #pragma unroll
        for (int j = 0; j < 32; j += 4) {
            float4 w = *(const float4*)&w1s[k * 32 + j];
            t[j + 0] += v * w.x;
            t[j + 1] += v * w.y;
            t[j + 2] += v * w.z;
            t[j + 3] += v * w.w;
        }
    }
    float s = b2s;
    #pragma unroll
    for (int j = 0; j < 32; j++) s += fmaxf(t[j], 0.f) * w2s[j];
    out[n] = s;
}

// ------------------------------ launch ---------------------------------------
extern "C" void kernel_launch(void* const* d_in, const int* in_sizes, int n_in,
                              void* d_out, int out_size)
{
    const float* x    = (const float*)d_in[0];
    const int*   ei   = (const int*)d_in[1];
    const float* W_in = (const float*)d_in[2];
    const float* b_in = (const float*)d_in[3];
    const float* W1   = (const float*)d_in[4];
    const float* as1  = (const float*)d_in[5];
    const float* ad1  = (const float*)d_in[6];
    const float* b1   = (const float*)d_in[7];
    const float* W2   = (const float*)d_in[8];
    const float* as2  = (const float*)d_in[9];
    const float* ad2  = (const float*)d_in[10];
    const float* b2   = (const float*)d_in[11];
    const float* W3   = (const float*)d_in[12];
    const float* as3  = (const float*)d_in[13];
    const float* ad3  = (const float*)d_in[14];
    const float* b3   = (const float*)d_in[15];
    const float* Ws1  = (const float*)d_in[16];
    const float* bs1  = (const float*)d_in[17];
    const float* Ws2  = (const float*)d_in[18];
    const float* bs2  = (const float*)d_in[19];
    float* out = (float*)d_out;

    float *px0, *pagg, *po1, *ph2, *po2, *ph3, *po3;
    float *pls1, *pld1, *pls2, *pld2, *pls3, *pld3;
    __nv_bfloat16 *pwth, *pwtl;
    cudaGetSymbolAddress((void**)&px0,  g_x0);
    cudaGetSymbolAddress((void**)&pagg, g_agg);
    cudaGetSymbolAddress((void**)&po1,  g_o1);
    cudaGetSymbolAddress((void**)&ph2,  g_h2);
    cudaGetSymbolAddress((void**)&po2,  g_o2);
    cudaGetSymbolAddress((void**)&ph3,  g_h3);
    cudaGetSymbolAddress((void**)&po3,  g_o3);
    cudaGetSymbolAddress((void**)&pls1, g_ls1);
    cudaGetSymbolAddress((void**)&pld1, g_ld1);
    cudaGetSymbolAddress((void**)&pls2, g_ls2);
    cudaGetSymbolAddress((void**)&pld2, g_ld2);
    cudaGetSymbolAddress((void**)&pls3, g_ls3);
    cudaGetSymbolAddress((void**)&pld3, g_ld3);
    cudaGetSymbolAddress((void**)&pwth, g_wth);
    cudaGetSymbolAddress((void**)&pwtl, g_wtl);

    // --- layer 0 + CSR begin (profiled capture slot 3 = gemm0) ---
    k_cvtW<<<(72 * 256 + 255) / 256, 256>>>(W_in, pwth, pwtl, 256, 72, 256);  // 0
    k_init_deg<<<(NN + 255) / 256, 256>>>();                                  // 1
    k_count_deg<<<(EE + 255) / 256, 256>>>(ei);                               // 2
    k_mmagemm<<<dim3(391, 1), 384>>>(x, 256, 0, pwth, pwtl, b_in, px0,
                                     nullptr, nullptr, nullptr, nullptr, 1,
                                     NN, 256, 72, 1, 0);                      // 3 (profiled)
    k_scan_blk<<<NBLK, 256>>>();
    k_scan_top<<<1, 256>>>();
    k_add_self<<<(NN + 255) / 256, 256>>>();
    k_scatter<<<(EE + 255) / 256, 256>>>(ei);

    // --- layer 1 ---
    k_cvec<<<3, 256>>>(W1, as1, ad1);
    k_logits8<<<(NN + 255) / 256, 256>>>(px0, pls1, pld1);
    k_edge4agg<<<(NN * 32) / 256, 256>>>(px0, pls1, pld1, pagg);
    k_cvtW<<<(288 * 96 + 255) / 256, 256>>>(W1, pwth, pwtl, 72, 288, 96);
    k_mmagemm<<<dim3(391, 4), 384>>>(pagg, 288, 1, pwth, pwtl, b1, po1,
                                     nullptr, nullptr, nullptr, nullptr, 1,
                                     NN, 72, 288, 1, 1);

    // --- layer 2 ---
    k_cvtW<<<(72 * 288 + 255) / 256, 256>>>(W2, pwth, pwtl, 288, 72, 288);
    k_mmagemm<<<dim3(391, 1), 384>>>(po1, 288, 0, pwth, pwtl, nullptr, ph2,
                                     as2, ad2, pls2, pld2, 1,
                                     NN, 288, 72, 0, 0);
    k_edge1<<<(NN * 32) / 256, 256>>>(ph2, pls2, pld2, b2, po2);

    // --- layer 3 ---
    k_cvtW<<<(72 * 96 + 255) / 256, 256>>>(W3, pwth, pwtl, 72, 72, 96);
    k_mmagemm<<<dim3(391, 1), 384>>>(po2, 72, 0, pwth, pwtl, nullptr, ph3,
                                     as3, ad3, pls3, pld3, 1,
                                     NN, 72, 72, 0, 0);
    k_edge1<<<(NN * 32) / 256, 256>>>(ph3, pls3, pld3, b3, po3);

    // --- residual + score MLP ---
    k_final<<<(NN + 255) / 256, 256>>>(po3, px0, Ws1, bs1, Ws2, bs2, out);
}